// round 5
// baseline (speedup 1.0000x reference)
#include <cuda_runtime.h>
#include <cuda_bf16.h>
#include <math.h>
#include <stdint.h>

// Problem constants
#define BB 2
#define LL 2048
#define DD 2048
#define HH 16
#define HD 128
#define MROWS (BB * LL)        // 4096
#define D3 (3 * DD)            // 6144
#define D8 (8 * DD)            // 16384
#define D4 (4 * DD)            // 8192

// ---------------- scratch ----------------
__device__ float g_qkv[(size_t)MROWS * D3];
__device__ float g_s  [(size_t)BB * HH * LL * LL];
__device__ float g_x1 [(size_t)MROWS * DD];
__device__ float g_p  [(size_t)MROWS * D8];
__device__ float g_cos[LL * 64];
__device__ float g_sin[LL * 64];

__device__ __align__(16) __nv_bfloat16 g_ah[(size_t)MROWS * D4];
__device__ __align__(16) __nv_bfloat16 g_al[(size_t)MROWS * D4];

__device__ __align__(16) __nv_bfloat16 g_qh[(size_t)BB * HH * LL * HD];
__device__ __align__(16) __nv_bfloat16 g_ql[(size_t)BB * HH * LL * HD];
__device__ __align__(16) __nv_bfloat16 g_kh[(size_t)BB * HH * LL * HD];
__device__ __align__(16) __nv_bfloat16 g_kl[(size_t)BB * HH * LL * HD];
__device__ __align__(16) __nv_bfloat16 g_vth[(size_t)BB * HH * HD * LL];
__device__ __align__(16) __nv_bfloat16 g_vtl[(size_t)BB * HH * HD * LL];
__device__ __align__(16) __nv_bfloat16 g_ph[(size_t)BB * HH * LL * LL];
__device__ __align__(16) __nv_bfloat16 g_pl[(size_t)BB * HH * LL * LL];

__device__ __align__(16) __nv_bfloat16 g_WqkvT_hi[(size_t)D3 * DD];
__device__ __align__(16) __nv_bfloat16 g_WqkvT_lo[(size_t)D3 * DD];
__device__ __align__(16) __nv_bfloat16 g_WoT_hi[(size_t)DD * DD];
__device__ __align__(16) __nv_bfloat16 g_WoT_lo[(size_t)DD * DD];
__device__ __align__(16) __nv_bfloat16 g_WpT_hi[(size_t)D8 * DD];
__device__ __align__(16) __nv_bfloat16 g_WpT_lo[(size_t)D8 * DD];
__device__ __align__(16) __nv_bfloat16 g_WffT_hi[(size_t)DD * D4];
__device__ __align__(16) __nv_bfloat16 g_WffT_lo[(size_t)DD * D4];

// ================= helpers =================
__device__ __forceinline__ uint32_t smem_u32(const void* p) {
    uint32_t a;
    asm("{ .reg .u64 t; cvta.to.shared.u64 t, %1; cvt.u32.u64 %0, t; }" : "=r"(a) : "l"(p));
    return a;
}

#define CP_ASYNC16(dst, src) \
    asm volatile("cp.async.cg.shared.global [%0], [%1], 16;" :: "r"(dst), "l"(src) : "memory")
#define CP_COMMIT() asm volatile("cp.async.commit_group;" ::: "memory")
#define CP_WAIT2()  asm volatile("cp.async.wait_group 2;" ::: "memory")
#define CP_WAIT1()  asm volatile("cp.async.wait_group 1;" ::: "memory")

#define LDSM4(r, addr) \
    asm volatile("ldmatrix.sync.aligned.m8n8.x4.shared.b16 {%0,%1,%2,%3}, [%4];" \
        : "=r"((r)[0]), "=r"((r)[1]), "=r"((r)[2]), "=r"((r)[3]) : "r"(addr))

#define MMA_BF16(d, a, b0, b1) \
    asm volatile("mma.sync.aligned.m16n8k16.row.col.f32.bf16.bf16.f32 " \
        "{%0,%1,%2,%3}, {%4,%5,%6,%7}, {%8,%9}, {%0,%1,%2,%3};" \
        : "+f"((d)[0]), "+f"((d)[1]), "+f"((d)[2]), "+f"((d)[3]) \
        : "r"((a)[0]), "r"((a)[1]), "r"((a)[2]), "r"((a)[3]), "r"(b0), "r"(b1))

// ================= RoPE tables =================
__global__ void rope_table_kernel() {
    int p = blockIdx.x, i = threadIdx.x;
    double inv_freq = pow(10000.0, -(double)(2 * i) / (double)HD);
    double ang = (double)p * inv_freq;
    g_cos[p * 64 + i] = (float)cos(ang);
    g_sin[p * 64 + i] = (float)sin(ang);
}

// ================= RMSNorm -> split bf16 hi/lo =================
__global__ void rmsnorm_split_kernel(const float* __restrict__ x,
                                     const float* __restrict__ g,
                                     __nv_bfloat16* __restrict__ hi,
                                     __nv_bfloat16* __restrict__ lo) {
    int row = blockIdx.x;
    const float* xr = x + (size_t)row * DD;
    float ss = 0.f;
    for (int c = threadIdx.x * 4; c < DD; c += blockDim.x * 4) {
        float4 v = *(const float4*)(xr + c);
        ss += v.x * v.x + v.y * v.y + v.z * v.z + v.w * v.w;
    }
    __shared__ float red[256];
    red[threadIdx.x] = ss;
    __syncthreads();
    for (int s = blockDim.x / 2; s > 0; s >>= 1) {
        if (threadIdx.x < s) red[threadIdx.x] += red[threadIdx.x + s];
        __syncthreads();
    }
    float scale = rsqrtf(red[0] / (float)DD + 1e-8f);
    for (int c = threadIdx.x * 4; c < DD; c += blockDim.x * 4) {
        float4 v = *(const float4*)(xr + c);
        float4 gv = *(const float4*)(g + c);
        float y[4] = {v.x * scale * gv.x, v.y * scale * gv.y,
                      v.z * scale * gv.z, v.w * scale * gv.w};
#pragma unroll
        for (int j = 0; j < 4; j++) {
            __nv_bfloat16 h = __float2bfloat16(y[j]);
            hi[(size_t)row * DD + c + j] = h;
            lo[(size_t)row * DD + c + j] = __float2bfloat16(y[j] - __bfloat162float(h));
        }
    }
}

// ================= weight transpose + split =================
__global__ void transpose_split_kernel(const float* __restrict__ W,
                                       __nv_bfloat16* __restrict__ Thi,
                                       __nv_bfloat16* __restrict__ Tlo,
                                       int K, int N) {
    __shared__ float t[32][33];
    int n0 = blockIdx.x * 32, k0 = blockIdx.y * 32;
    int tx = threadIdx.x, ty = threadIdx.y;
#pragma unroll
    for (int r = 0; r < 4; r++) {
        int k = ty + r * 8;
        t[k][tx] = W[(size_t)(k0 + k) * N + n0 + tx];
    }
    __syncthreads();
#pragma unroll
    for (int r = 0; r < 4; r++) {
        int n = ty + r * 8;
        float v = t[tx][n];
        __nv_bfloat16 h = __float2bfloat16(v);
        Thi[(size_t)(n0 + n) * K + k0 + tx] = h;
        Tlo[(size_t)(n0 + n) * K + k0 + tx] = __float2bfloat16(v - __bfloat162float(h));
    }
}

// ================= mma.sync bf16x3 GEMM: 128x256 tile, 512 threads =================
#define TM 128
#define TN 256
#define KC 32
#define AHI_OFF 0
#define ALO_OFF 8192
#define BHI_OFF 16384
#define BLO_OFF 32768
#define STG_BYTES 49152
#define GEMM_SMEM (3 * STG_BYTES)

__global__ void __launch_bounds__(512, 1) gemm_mma3_kernel(
    const __nv_bfloat16* __restrict__ Ahi, const __nv_bfloat16* __restrict__ Alo,
    const __nv_bfloat16* __restrict__ Bhi, const __nv_bfloat16* __restrict__ Blo,
    const float* __restrict__ bias, const float* __restrict__ R,
    float* __restrict__ C, int M, int N, int K)
{
    extern __shared__ char sm[];
    const int tid = threadIdx.x;
    const int lane = tid & 31;
    const int wid = tid >> 5;
    const int wm = wid & 3;        // 4 warp-rows of 32
    const int wn = wid >> 2;       // 4 warp-cols of 64
    const int bm = blockIdx.x * TM;
    const int bn = blockIdx.y * TN;
    const uint32_t smb = smem_u32(sm);

    const int rowA_base = wm * 32 + (lane & 15);
    const int rowB_base = wn * 64 + (lane & 7) + ((lane >> 4) << 3);
    const uint32_t xorw = (uint32_t)((lane & 6) << 3);

    float acc[2][8][4];
#pragma unroll
    for (int i = 0; i < 2; i++)
#pragma unroll
        for (int j = 0; j < 8; j++)
#pragma unroll
            for (int q = 0; q < 4; q++) acc[i][j][q] = 0.f;

    auto issue_chunk = [&](int k0, int stg) {
        const uint32_t sbase = smb + stg * STG_BYTES;
#pragma unroll
        for (int i = 0; i < 6; i++) {
            int u = tid + (i << 9);
            const __nv_bfloat16* src;
            uint32_t roff;
            int row;
            if (u < 512)       { row = u >> 2;          src = Ahi + (size_t)(bm + row) * K; roff = AHI_OFF; }
            else if (u < 1024) { row = (u - 512) >> 2;  src = Alo + (size_t)(bm + row) * K; roff = ALO_OFF; }
            else if (u < 2048) { row = (u - 1024) >> 2; src = Bhi + (size_t)(bn + row) * K; roff = BHI_OFF; }
            else               { row = (u - 2048) >> 2; src = Blo + (size_t)(bn + row) * K; roff = BLO_OFF; }
            int seg = u & 3;
            uint32_t dst = sbase + roff + (uint32_t)(row * 64) +
                           (((uint32_t)(seg * 16)) ^ ((uint32_t)((row & 6) << 3)));
            CP_ASYNC16(dst, src + k0 + seg * 8);
        }
        CP_COMMIT();
    };

    const int NC = K / KC;
    issue_chunk(0, 0);
    issue_chunk(KC, 1);
    issue_chunk(2 * KC, 2);

    for (int c = 0; c < NC; ++c) {
        CP_WAIT2();
        __syncthreads();
        const uint32_t stg = smb + (uint32_t)((c % 3) * STG_BYTES);

#pragma unroll
        for (int kk = 0; kk < 2; kk++) {
            const uint32_t cbA = ((uint32_t)(kk * 32 + ((lane >> 4) << 4))) ^ xorw;
            const uint32_t cbB = ((uint32_t)(kk * 32 + (((lane >> 3) & 1) << 4))) ^ xorw;

            uint32_t ah[2][4], bh4[4][4], fa[2][4], fb[4][4];
#pragma unroll
            for (int mt = 0; mt < 2; mt++)
                LDSM4(ah[mt], stg + AHI_OFF + (uint32_t)((rowA_base + mt * 16) * 64) + cbA);
#pragma unroll
            for (int bt = 0; bt < 4; bt++)
                LDSM4(bh4[bt], stg + BHI_OFF + (uint32_t)((rowB_base + bt * 16) * 64) + cbB);
            // hi x hi
#pragma unroll
            for (int mt = 0; mt < 2; mt++)
#pragma unroll
                for (int nt = 0; nt < 8; nt++) {
                    const uint32_t* b = bh4[nt >> 1];
                    if (nt & 1) MMA_BF16(acc[mt][nt], ah[mt], b[2], b[3]);
                    else        MMA_BF16(acc[mt][nt], ah[mt], b[0], b[1]);
                }
            // lo x hi (reuse bh4)
#pragma unroll
            for (int mt = 0; mt < 2; mt++)
                LDSM4(fa[mt], stg + ALO_OFF + (uint32_t)((rowA_base + mt * 16) * 64) + cbA);
#pragma unroll
            for (int mt = 0; mt < 2; mt++)
#pragma unroll
                for (int nt = 0; nt < 8; nt++) {
                    const uint32_t* b = bh4[nt >> 1];
                    if (nt & 1) MMA_BF16(acc[mt][nt], fa[mt], b[2], b[3]);
                    else        MMA_BF16(acc[mt][nt], fa[mt], b[0], b[1]);
                }
            // hi x lo
#pragma unroll
            for (int bt = 0; bt < 4; bt++)
                LDSM4(fb[bt], stg + BLO_OFF + (uint32_t)((rowB_base + bt * 16) * 64) + cbB);
#pragma unroll
            for (int mt = 0; mt < 2; mt++)
#pragma unroll
                for (int nt = 0; nt < 8; nt++) {
                    const uint32_t* b = fb[nt >> 1];
                    if (nt & 1) MMA_BF16(acc[mt][nt], ah[mt], b[2], b[3]);
                    else        MMA_BF16(acc[mt][nt], ah[mt], b[0], b[1]);
                }
        }

        __syncthreads();
        if (c + 3 < NC) issue_chunk((c + 3) * KC, (c + 3) % 3);
        else CP_COMMIT();
    }

    // ---- epilogue ----
#pragma unroll
    for (int mt = 0; mt < 2; mt++) {
        const int m = bm + wm * 32 + mt * 16 + (lane >> 2);
#pragma unroll
        for (int nt = 0; nt < 8; nt++) {
            const int n = bn + wn * 64 + nt * 8 + ((lane & 3) << 1);
            float2 b2 = *(const float2*)(bias + n);
            float2 o0, o1;
            o0.x = acc[mt][nt][0] + b2.x;
            o0.y = acc[mt][nt][1] + b2.y;
            o1.x = acc[mt][nt][2] + b2.x;
            o1.y = acc[mt][nt][3] + b2.y;
            if (R) {
                float2 r0 = *(const float2*)(R + (size_t)m * N + n);
                float2 r1 = *(const float2*)(R + (size_t)(m + 8) * N + n);
                o0.x += r0.x; o0.y += r0.y;
                o1.x += r1.x; o1.y += r1.y;
            }
            *(float2*)(C + (size_t)m * N + n) = o0;
            *(float2*)(C + (size_t)(m + 8) * N + n) = o1;
        }
    }
}

// ================= RoPE: qkv fp32 -> split bf16 q,k in [B,H,L,HD] =================
__global__ void rope_apply_split_kernel() {
    int idx = blockIdx.x * blockDim.x + threadIdx.x;
    if (idx >= BB * LL * HH * 64) return;
    int d = idx & 63;
    int h = (idx >> 6) & (HH - 1);
    int bl = idx >> 10;
    int b = bl >> 11;
    int l = bl & (LL - 1);
    float c = g_cos[l * 64 + d];
    float s = g_sin[l * 64 + d];
    size_t src = (size_t)bl * D3 + h * HD + d;
    size_t dst = ((size_t)(b * HH + h) * LL + l) * HD + d;

    float q1 = g_qkv[src], q2 = g_qkv[src + 64];
    float qa = q1 * c - q2 * s;
    float qb = q2 * c + q1 * s;
    __nv_bfloat16 t;
    t = __float2bfloat16(qa); g_qh[dst] = t;      g_ql[dst] = __float2bfloat16(qa - __bfloat162float(t));
    t = __float2bfloat16(qb); g_qh[dst + 64] = t; g_ql[dst + 64] = __float2bfloat16(qb - __bfloat162float(t));

    size_t ks = src + DD;
    float k1 = g_qkv[ks], k2 = g_qkv[ks + 64];
    float ka = k1 * c - k2 * s;
    float kb = k2 * c + k1 * s;
    t = __float2bfloat16(ka); g_kh[dst] = t;      g_kl[dst] = __float2bfloat16(ka - __bfloat162float(t));
    t = __float2bfloat16(kb); g_kh[dst + 64] = t; g_kl[dst + 64] = __float2bfloat16(kb - __bfloat162float(t));
}

// ================= V transpose + split =================
__global__ void v_transpose_split_kernel() {
    __shared__ float t[32][33];
    int l0 = blockIdx.x * 32, d0 = blockIdx.y * 32, bh = blockIdx.z;
    int b = bh >> 4, h = bh & 15;
    int tx = threadIdx.x, ty = threadIdx.y;
#pragma unroll
    for (int r = 0; r < 4; r++) {
        int l = ty + r * 8;
        t[l][tx] = g_qkv[(size_t)(b * LL + l0 + l) * D3 + 2 * DD + h * HD + d0 + tx];
    }
    __syncthreads();
#pragma unroll
    for (int r = 0; r < 4; r++) {
        int d = ty + r * 8;
        float v = t[tx][d];
        __nv_bfloat16 hv = __float2bfloat16(v);
        size_t dst = ((size_t)bh * HD + d0 + d) * LL + l0 + tx;
        g_vth[dst] = hv;
        g_vtl[dst] = __float2bfloat16(v - __bfloat162float(hv));
    }
}

// ================= attention scores (bf16x3 MMA) =================
#define ATT_STG 32768
#define ATT_SMEM (2 * ATT_STG)

__global__ void __launch_bounds__(256, 1) attn_scores_mma_kernel() {
    extern __shared__ char sm[];
    const int jb = blockIdx.x, ib = blockIdx.y, bh = blockIdx.z;
    if (jb > ib) return;
    const int tid = threadIdx.x, lane = tid & 31, wid = tid >> 5;
    const int wm = wid & 3, wn = wid >> 2;
    const uint32_t smb = smem_u32(sm);

    const __nv_bfloat16* Qh = g_qh + ((size_t)bh * LL + ib * 128) * HD;
    const __nv_bfloat16* Ql = g_ql + ((size_t)bh * LL + ib * 128) * HD;
    const __nv_bfloat16* Kh = g_kh + ((size_t)bh * LL + jb * 128) * HD;
    const __nv_bfloat16* Kl = g_kl + ((size_t)bh * LL + jb * 128) * HD;

    const int rowA_base = wm * 32 + (lane & 15);
    const int rowB_base = wn * 64 + (lane & 7) + ((lane >> 4) << 3);
    const uint32_t xorw = (uint32_t)((lane & 6) << 3);

    float acc[2][8][4];
#pragma unroll
    for (int i = 0; i < 2; i++)
#pragma unroll
        for (int j = 0; j < 8; j++)
#pragma unroll
            for (int q = 0; q < 4; q++) acc[i][j][q] = 0.f;

    auto issue = [&](int c, int stg) {
        const uint32_t sb = smb + (uint32_t)(stg * ATT_STG);
        const int k0 = c * 32;
#pragma unroll
        for (int i = 0; i < 8; i++) {
            int u = tid + (i << 8);
            int row = (u >> 2) & 127;
            int seg = u & 3;
            const __nv_bfloat16* src = (u < 512) ? Qh : (u < 1024) ? Ql : (u < 1536) ? Kh : Kl;
            uint32_t roff = (uint32_t)(u >> 9) * 8192;
            uint32_t dst = sb + roff + (uint32_t)(row * 64) +
                           (((uint32_t)(seg * 16)) ^ ((uint32_t)((row & 6) << 3)));
            CP_ASYNC16(dst, src + (size_t)row * HD + k0 + seg * 8);
        }
        CP_COMMIT();
    };

    issue(0, 0);
    issue(1, 1);
#pragma unroll 1
    for (int c = 0; c < 4; c++) {
        CP_WAIT1();
        __syncthreads();
        const uint32_t stg = smb + (uint32_t)((c & 1) * ATT_STG);
#pragma unroll
        for (int kk = 0; kk < 2; kk++) {
            const uint32_t cbA = ((uint32_t)(kk * 32 + ((lane >> 4) << 4))) ^ xorw;
            const uint32_t cbB = ((uint32_t)(kk * 32 + (((lane >> 3) & 1) << 4))) ^ xorw;
            uint32_t ah[2][4], bh4[4][4], fb[4][4], fa[2][4];
#pragma unroll
            for (int mt = 0; mt < 2; mt++)
                LDSM4(ah[mt], stg + 0 + (uint32_t)((rowA_base + mt * 16) * 64) + cbA);
#pragma unroll
            for (int bt = 0; bt < 4; bt++)
                LDSM4(bh4[bt], stg + 16384 + (uint32_t)((rowB_base + bt * 16) * 64) + cbB);
#pragma unroll
            for (int mt = 0; mt < 2; mt++)
#pragma unroll
                for (int nt = 0; nt < 8; nt++) {
                    const uint32_t* b = bh4[nt >> 1];
                    if (nt & 1) MMA_BF16(acc[mt][nt], ah[mt], b[2], b[3]);
                    else        MMA_BF16(acc[mt][nt], ah[mt], b[0], b[1]);
                }
#pragma unroll
            for (int mt = 0; mt < 2; mt++)
                LDSM4(fa[mt], stg + 8192 + (uint32_t)((rowA_base + mt * 16) * 64) + cbA);
#pragma unroll
            for (int mt = 0; mt < 2; mt++)
#pragma unroll
                for (int nt = 0; nt < 8; nt++) {
                    const uint32_t* b = bh4[nt >> 1];
                    if (nt & 1) MMA_BF16(acc[mt][nt], fa[mt], b[2], b[3]);
                    else        MMA_BF16(acc[mt][nt], fa[mt], b[0], b[1]);
                }
#pragma unroll
            for (int bt = 0; bt < 4; bt++)
                LDSM4(fb[bt], stg + 24576 + (uint32_t)((rowB_base + bt * 16) * 64) + cbB);
#pragma unroll
            for (int mt = 0; mt < 2; mt++)
#pragma unroll
                for (int nt = 0; nt < 8; nt++) {
                    const uint32_t* b = fb[nt >> 1];
                    if (nt & 1) MMA_BF16(acc[mt][nt], ah[mt], b[2], b[3]);
                    else        MMA_BF16(acc[mt][nt], ah[mt], b[0], b[1]);
                }
        }
        __syncthreads();
        if (c + 2 < 4) issue(c + 2, c & 1);
        else CP_COMMIT();
    }

    const float scale = 0.08838834764831845f;
#pragma unroll
    for (int mt = 0; mt < 2; mt++) {
        const int i0 = ib * 128 + wm * 32 + mt * 16 + (lane >> 2);
#pragma unroll
        for (int nt = 0; nt < 8; nt++) {
            const int j0 = jb * 128 + wn * 64 + nt * 8 + ((lane & 3) << 1);
            float2 o0, o1;
            o0.x = (j0     <= i0)     ? acc[mt][nt][0] * scale : -1e30f;
            o0.y = (j0 + 1 <= i0)     ? acc[mt][nt][1] * scale : -1e30f;
            o1.x = (j0     <= i0 + 8) ? acc[mt][nt][2] * scale : -1e30f;
            o1.y = (j0 + 1 <= i0 + 8) ? acc[mt][nt][3] * scale : -1e30f;
            *(float2*)(g_s + ((size_t)bh * LL + i0) * LL + j0) = o0;
            *(float2*)(g_s + ((size_t)bh * LL + i0 + 8) * LL + j0) = o1;
        }
    }
}

// ================= row softmax -> split bf16 P =================
__global__ void softmax_kernel() {
    int r = blockIdx.x;
    int i = r & (LL - 1);
    int len = ((i >> 6) + 1) << 6;
    int len2 = ((i >> 7) + 1) << 7;
    float* p = g_s + (size_t)r * LL;
    __nv_bfloat16* ph = g_ph + (size_t)r * LL;
    __nv_bfloat16* pl = g_pl + (size_t)r * LL;
    __shared__ float red[128];

    float m = -1e30f;
    for (int c = threadIdx.x; c < len; c += 128) m = fmaxf(m, p[c]);
    red[threadIdx.x] = m;
    __syncthreads();
    for (int s = 64; s > 0; s >>= 1) {
        if (threadIdx.x < s) red[threadIdx.x] = fmaxf(red[threadIdx.x], red[threadIdx.x + s]);
        __syncthreads();
    }
    m = red[0];
    __syncthreads();

    float sum = 0.f;
    for (int c = threadIdx.x; c < len; c += 128) {
        float e = expf(p[c] - m);
        p[c] = e;
        sum += e;
    }
    red[threadIdx.x] = sum;
    __syncthreads();
    for (int s = 64; s > 0; s >>= 1) {
        if (threadIdx.x < s) red[threadIdx.x] += red[threadIdx.x + s];
        __syncthreads();
    }
    float inv = 1.f / red[0];
    for (int c = threadIdx.x; c < len; c += 128) {
        float v = p[c] * inv;
        __nv_bfloat16 hv = __float2bfloat16(v);
        ph[c] = hv;
        pl[c] = __float2bfloat16(v - __bfloat162float(hv));
    }
    for (int c = len + threadIdx.x; c < len2; c += 128) {
        ph[c] = __float2bfloat16(0.f);
        pl[c] = __float2bfloat16(0.f);
    }
}

// ================= O = P @ V (bf16x3 MMA) -> split o =================
__global__ void __launch_bounds__(256, 1) attn_pv_mma_kernel() {
    extern __shared__ char sm[];
    const int ib = blockIdx.x, bh = blockIdx.y;
    const int b = bh >> 4, h = bh & 15;
    const int tid = threadIdx.x, lane = tid & 31, wid = tid >> 5;
    const int wm = wid & 3, wn = wid >> 2;
    const uint32_t smb = smem_u32(sm);

    const __nv_bfloat16* Ph = g_ph + ((size_t)bh * LL + ib * 128) * LL;
    const __nv_bfloat16* Pl = g_pl + ((size_t)bh * LL + ib * 128) * LL;
    const __nv_bfloat16* Vh = g_vth + (size_t)bh * HD * LL;
    const __nv_bfloat16* Vl = g_vtl + (size_t)bh * HD * LL;

    const int rowA_base = wm * 32 + (lane & 15);
    const int rowB_base = wn * 64 + (lane & 7) + ((lane >> 4) << 3);
    const uint32_t xorw = (uint32_t)((lane & 6) << 3);

    float acc[2][8][4];
#pragma unroll
    for (int i = 0; i < 2; i++)
#pragma unroll
        for (int j = 0; j < 8; j++)
#pragma unroll
            for (int q = 0; q < 4; q++) acc[i][j][q] = 0.f;

    auto issue = [&](int c, int stg) {
        const uint32_t sb = smb + (uint32_t)(stg * ATT_STG);
        const int j0 = c * 32;
#pragma unroll
        for (int i = 0; i < 8; i++) {
            int u = tid + (i << 8);
            int row = (u >> 2) & 127;
            int seg = u & 3;
            const __nv_bfloat16* src = (u < 512) ? Ph : (u < 1024) ? Pl : (u < 1536) ? Vh : Vl;
            uint32_t roff = (uint32_t)(u >> 9) * 8192;
            uint32_t dst = sb + roff + (uint32_t)(row * 64) +
                           (((uint32_t)(seg * 16)) ^ ((uint32_t)((row & 6) << 3)));
            CP_ASYNC16(dst, src + (size_t)row * LL + j0 + seg * 8);
        }
        CP_COMMIT();
    };

    const int NC = (ib + 1) * 4;
    issue(0, 0);
    issue(1, 1);
#pragma unroll 1
    for (int c = 0; c < NC; c++) {
        CP_WAIT1();
        __syncthreads();
        const uint32_t stg = smb + (uint32_t)((c & 1) * ATT_STG);
#pragma unroll
        for (int kk = 0; kk < 2; kk++) {
            const uint32_t cbA = ((uint32_t)(kk * 32 + ((lane >> 4) << 4))) ^ xorw;
            const uint32_t cbB = ((uint32_t)(kk * 32 + (((lane >> 3) & 1) << 4))) ^ xorw;
            uint32_t ah[2][4], bh4[4][4], fb[4][4], fa[2][4];
#pragma unroll
            for (int mt = 0; mt < 2; mt++)
                LDSM4(ah[mt], stg + 0 + (uint32_t)((rowA_base + mt * 16) * 64) + cbA);
#pragma unroll
            for (int bt = 0; bt < 4; bt++)
                LDSM4(bh4[bt], stg + 16384 + (uint32_t)((rowB_base + bt * 16) * 64) + cbB);
#pragma unroll
            for (int mt = 0; mt < 2; mt++)
#pragma unroll
                for (int nt = 0; nt < 8; nt++) {
                    const uint32_t* bb = bh4[nt >> 1];
                    if (nt & 1) MMA_BF16(acc[mt][nt], ah[mt], bb[2], bb[3]);
                    else        MMA_BF16(acc[mt][nt], ah[mt], bb[0], bb[1]);
                }
#pragma unroll
            for (int mt = 0; mt < 2; mt++)
                LDSM4(fa[mt], stg + 8192 + (uint32_t)((rowA_base + mt * 16) * 64) + cbA);
#pragma unroll
            for (int mt = 0; mt < 2; mt++)
#pragma unroll
                for (int nt = 0; nt < 8; nt++) {
                    const uint32_t* bb = bh4[nt >> 1];
                    if (nt & 1) MMA_BF16(acc[mt][nt], fa[mt], bb[2], bb[3]);
                    else        MMA_BF16(acc[mt][nt], fa[mt], bb[0], bb[1]);
                }
#pragma unroll
            for (int bt = 0; bt < 4; bt++)
                LDSM4(fb[bt], stg + 24576 + (uint32_t)((rowB_base + bt * 16) * 64) + cbB);
#pragma unroll
            for (int mt = 0; mt < 2; mt++)
#pragma unroll
                for (int nt = 0; nt < 8; nt++) {
                    const uint32_t* bb = fb[nt >> 1];
                    if (nt & 1) MMA_BF16(acc[mt][nt], ah[mt], bb[2], bb[3]);
                    else        MMA_BF16(acc[mt][nt], ah[mt], bb[0], bb[1]);
                }
        }
        __syncthreads();
        if (c + 2 < NC) issue(c + 2, c & 1);
        else CP_COMMIT();
    }

#pragma unroll
    for (int mt = 0; mt < 2; mt++) {
        const int qi = ib * 128 + wm * 32 + mt * 16 + (lane >> 2);
#pragma unroll
        for (int nt = 0; nt < 8; nt++) {
            const int d = wn * 64 + nt * 8 + ((lane & 3) << 1);
            size_t base0 = (size_t)(b * LL + qi) * DD + h * HD + d;
            size_t base1 = (size_t)(b * LL + qi + 8) * DD + h * HD + d;
            float v0 = acc[mt][nt][0], v1 = acc[mt][nt][1];
            float v2 = acc[mt][nt][2], v3 = acc[mt][nt][3];
            __nv_bfloat16 h0 = __float2bfloat16(v0), h1 = __float2bfloat16(v1);
            __nv_bfloat16 h2 = __float2bfloat16(v2), h3 = __float2bfloat16(v3);
            *(__nv_bfloat162*)(g_ah + base0) = __halves2bfloat162(h0, h1);
            *(__nv_bfloat162*)(g_ah + base1) = __halves2bfloat162(h2, h3);
            *(__nv_bfloat162*)(g_al + base0) = __halves2bfloat162(
                __float2bfloat16(v0 - __bfloat162float(h0)),
                __float2bfloat16(v1 - __bfloat162float(h1)));
            *(__nv_bfloat162*)(g_al + base1) = __halves2bfloat162(
                __float2bfloat16(v2 - __bfloat162float(h2)),
                __float2bfloat16(v3 - __bfloat162float(h3)));
        }
    }
}

// ================= SwiGLU -> split bf16 =================
__global__ void swiglu_split_kernel() {
    size_t idx = (size_t)blockIdx.x * blockDim.x + threadIdx.x;
    if (idx >= (size_t)MROWS * D4) return;
    size_t row = idx >> 13;
    int col = (int)(idx & (D4 - 1));
    float gv = g_p[row * D8 + col];
    float vv = g_p[row * D8 + D4 + col];
    float r = gv / (1.f + expf(-gv)) * vv;
    __nv_bfloat16 hv = __float2bfloat16(r);
    g_ah[idx] = hv;
    g_al[idx] = __float2bfloat16(r - __bfloat162float(hv));
}

// ================= launch =================
extern "C" void kernel_launch(void* const* d_in, const int* in_sizes, int n_in,
                              void* d_out, int out_size) {
    const float* x    = (const float*)d_in[0];
    const float* Wqkv = (const float*)d_in[1];
    const float* bqkv = (const float*)d_in[2];
    const float* Wo   = (const float*)d_in[3];
    const float* bo   = (const float*)d_in[4];
    const float* g1   = (const float*)d_in[5];
    const float* g2   = (const float*)d_in[6];
    const float* Wp   = (const float*)d_in[7];
    const float* bp   = (const float*)d_in[8];
    const float* Wff  = (const float*)d_in[9];
    const float* bff  = (const float*)d_in[10];
    float* out = (float*)d_out;

    __nv_bfloat16 *ah, *al, *wqh, *wql, *woh, *wol, *wph, *wpl, *wfh, *wfl;
    float *qkv, *x1, *p;
    cudaGetSymbolAddress((void**)&ah,  g_ah);
    cudaGetSymbolAddress((void**)&al,  g_al);
    cudaGetSymbolAddress((void**)&wqh, g_WqkvT_hi);
    cudaGetSymbolAddress((void**)&wql, g_WqkvT_lo);
    cudaGetSymbolAddress((void**)&woh, g_WoT_hi);
    cudaGetSymbolAddress((void**)&wol, g_WoT_lo);
    cudaGetSymbolAddress((void**)&wph, g_WpT_hi);
    cudaGetSymbolAddress((void**)&wpl, g_WpT_lo);
    cudaGetSymbolAddress((void**)&wfh, g_WffT_hi);
    cudaGetSymbolAddress((void**)&wfl, g_WffT_lo);
    cudaGetSymbolAddress((void**)&qkv, g_qkv);
    cudaGetSymbolAddress((void**)&x1,  g_x1);
    cudaGetSymbolAddress((void**)&p,   g_p);

    cudaFuncSetAttribute(gemm_mma3_kernel,
                         cudaFuncAttributeMaxDynamicSharedMemorySize, GEMM_SMEM);
    cudaFuncSetAttribute(attn_scores_mma_kernel,
                         cudaFuncAttributeMaxDynamicSharedMemorySize, ATT_SMEM);
    cudaFuncSetAttribute(attn_pv_mma_kernel,
                         cudaFuncAttributeMaxDynamicSharedMemorySize, ATT_SMEM);

    dim3 tb(32, 8);

    // 1) h = rms(x, g1), split
    rmsnorm_split_kernel<<<MROWS, 256>>>(x, g1, ah, al);
    // 2) Wqkv transpose/split
    transpose_split_kernel<<<dim3(D3 / 32, DD / 32), tb>>>(Wqkv, wqh, wql, DD, D3);
    // 3) RoPE tables
    rope_table_kernel<<<LL, 64>>>();
    // 4) qkv = h @ Wqkv + bqkv   (launch #4 — profiled)
    gemm_mma3_kernel<<<dim3(MROWS / TM, D3 / TN), 512, GEMM_SMEM>>>(
        ah, al, wqh, wql, bqkv, nullptr, qkv, MROWS, D3, DD);
    // 5) RoPE apply + split q,k
    {
        int total = BB * LL * HH * 64;
        rope_apply_split_kernel<<<(total + 255) / 256, 256>>>();
    }
    // 6) V transpose + split
    v_transpose_split_kernel<<<dim3(LL / 32, HD / 32, BB * HH), tb>>>();
    // 7) scores
    attn_scores_mma_kernel<<<dim3(LL / 128, LL / 128, BB * HH), 256, ATT_SMEM>>>();
    // 8) softmax -> split P
    softmax_kernel<<<BB * HH * LL, 128>>>();
    // 9) O = P @ V
    attn_pv_mma_kernel<<<dim3(LL / 128, BB * HH), 256, ATT_SMEM>>>();
    // 10) Wo transpose/split
    transpose_split_kernel<<<dim3(DD / 32, DD / 32), tb>>>(Wo, woh, wol, DD, DD);
    // 11) x1 = o @ Wo + bo + x
    gemm_mma3_kernel<<<dim3(MROWS / TM, DD / TN), 512, GEMM_SMEM>>>(
        ah, al, woh, wol, bo, x, x1, MROWS, DD, DD);
    // 12) h2 = rms(x1, g2), split
    rmsnorm_split_kernel<<<MROWS, 256>>>(x1, g2, ah, al);
    // 13) Wp transpose/split
    transpose_split_kernel<<<dim3(D8 / 32, DD / 32), tb>>>(Wp, wph, wpl, DD, D8);
    // 14) p = h2 @ Wp + bp
    gemm_mma3_kernel<<<dim3(MROWS / TM, D8 / TN), 512, GEMM_SMEM>>>(
        ah, al, wph, wpl, bp, nullptr, p, MROWS, D8, DD);
    // 15) ffh = silu(gate) * value, split
    {
        size_t total = (size_t)MROWS * D4;
        swiglu_split_kernel<<<(unsigned)((total + 255) / 256), 256>>>();
    }
    // 16) Wff transpose/split
    transpose_split_kernel<<<dim3(DD / 32, D4 / 32), tb>>>(Wff, wfh, wfl, D4, DD);
    // 17) out = ffh @ Wff + bff + x1
    gemm_mma3_kernel<<<dim3(MROWS / TM, DD / TN), 512, GEMM_SMEM>>>(
        ah, al, wfh, wfl, bff, x1, out, MROWS, DD, D4);
}

// round 6
// speedup vs baseline: 1.0903x; 1.0903x over previous
#include <cuda_runtime.h>
#include <cuda_bf16.h>
#include <math.h>
#include <stdint.h>

// Problem constants
#define BB 2
#define LL 2048
#define DD 2048
#define HH 16
#define HD 128
#define MROWS (BB * LL)        // 4096
#define D3 (3 * DD)            // 6144
#define D8 (8 * DD)            // 16384
#define D4 (4 * DD)            // 8192

// ---------------- scratch ----------------
__device__ float g_qkv[(size_t)MROWS * D3];
__device__ float g_s  [(size_t)BB * HH * LL * LL];
__device__ float g_x1 [(size_t)MROWS * DD];
__device__ float g_p  [(size_t)MROWS * D8];
__device__ float g_cos[LL * 64];
__device__ float g_sin[LL * 64];

__device__ __align__(16) __nv_bfloat16 g_ah[(size_t)MROWS * D4];
__device__ __align__(16) __nv_bfloat16 g_al[(size_t)MROWS * D4];

__device__ __align__(16) __nv_bfloat16 g_qh[(size_t)BB * HH * LL * HD];
__device__ __align__(16) __nv_bfloat16 g_ql[(size_t)BB * HH * LL * HD];
__device__ __align__(16) __nv_bfloat16 g_kh[(size_t)BB * HH * LL * HD];
__device__ __align__(16) __nv_bfloat16 g_kl[(size_t)BB * HH * LL * HD];
__device__ __align__(16) __nv_bfloat16 g_vth[(size_t)BB * HH * HD * LL];
__device__ __align__(16) __nv_bfloat16 g_vtl[(size_t)BB * HH * HD * LL];
__device__ __align__(16) __nv_bfloat16 g_ph[(size_t)BB * HH * LL * LL];
__device__ __align__(16) __nv_bfloat16 g_pl[(size_t)BB * HH * LL * LL];

__device__ __align__(16) __nv_bfloat16 g_WqkvT_hi[(size_t)D3 * DD];
__device__ __align__(16) __nv_bfloat16 g_WqkvT_lo[(size_t)D3 * DD];
__device__ __align__(16) __nv_bfloat16 g_WoT_hi[(size_t)DD * DD];
__device__ __align__(16) __nv_bfloat16 g_WoT_lo[(size_t)DD * DD];
__device__ __align__(16) __nv_bfloat16 g_WpT_hi[(size_t)D8 * DD];
__device__ __align__(16) __nv_bfloat16 g_WpT_lo[(size_t)D8 * DD];
__device__ __align__(16) __nv_bfloat16 g_WffT_hi[(size_t)DD * D4];
__device__ __align__(16) __nv_bfloat16 g_WffT_lo[(size_t)DD * D4];

// ================= helpers =================
__device__ __forceinline__ uint32_t smem_u32(const void* p) {
    uint32_t a;
    asm("{ .reg .u64 t; cvta.to.shared.u64 t, %1; cvt.u32.u64 %0, t; }" : "=r"(a) : "l"(p));
    return a;
}

#define CP_ASYNC16(dst, src) \
    asm volatile("cp.async.cg.shared.global [%0], [%1], 16;" :: "r"(dst), "l"(src) : "memory")
#define CP_COMMIT() asm volatile("cp.async.commit_group;" ::: "memory")
#define CP_WAIT2()  asm volatile("cp.async.wait_group 2;" ::: "memory")

#define LDSM4(r, addr) \
    asm volatile("ldmatrix.sync.aligned.m8n8.x4.shared.b16 {%0,%1,%2,%3}, [%4];" \
        : "=r"((r)[0]), "=r"((r)[1]), "=r"((r)[2]), "=r"((r)[3]) : "r"(addr))

#define MMA_BF16(d, a, b0, b1) \
    asm volatile("mma.sync.aligned.m16n8k16.row.col.f32.bf16.bf16.f32 " \
        "{%0,%1,%2,%3}, {%4,%5,%6,%7}, {%8,%9}, {%0,%1,%2,%3};" \
        : "+f"((d)[0]), "+f"((d)[1]), "+f"((d)[2]), "+f"((d)[3]) \
        : "r"((a)[0]), "r"((a)[1]), "r"((a)[2]), "r"((a)[3]), "r"(b0), "r"(b1))

// ================= RoPE tables =================
__global__ void rope_table_kernel() {
    int p = blockIdx.x, i = threadIdx.x;
    double inv_freq = pow(10000.0, -(double)(2 * i) / (double)HD);
    double ang = (double)p * inv_freq;
    g_cos[p * 64 + i] = (float)cos(ang);
    g_sin[p * 64 + i] = (float)sin(ang);
}

// ================= RMSNorm -> split bf16 hi/lo =================
__global__ void rmsnorm_split_kernel(const float* __restrict__ x,
                                     const float* __restrict__ g,
                                     __nv_bfloat16* __restrict__ hi,
                                     __nv_bfloat16* __restrict__ lo) {
    int row = blockIdx.x;
    const float* xr = x + (size_t)row * DD;
    float ss = 0.f;
    for (int c = threadIdx.x * 4; c < DD; c += blockDim.x * 4) {
        float4 v = *(const float4*)(xr + c);
        ss += v.x * v.x + v.y * v.y + v.z * v.z + v.w * v.w;
    }
    __shared__ float red[256];
    red[threadIdx.x] = ss;
    __syncthreads();
    for (int s = blockDim.x / 2; s > 0; s >>= 1) {
        if (threadIdx.x < s) red[threadIdx.x] += red[threadIdx.x + s];
        __syncthreads();
    }
    float scale = rsqrtf(red[0] / (float)DD + 1e-8f);
    for (int c = threadIdx.x * 4; c < DD; c += blockDim.x * 4) {
        float4 v = *(const float4*)(xr + c);
        float4 gv = *(const float4*)(g + c);
        float y[4] = {v.x * scale * gv.x, v.y * scale * gv.y,
                      v.z * scale * gv.z, v.w * scale * gv.w};
#pragma unroll
        for (int j = 0; j < 4; j++) {
            __nv_bfloat16 h = __float2bfloat16(y[j]);
            hi[(size_t)row * DD + c + j] = h;
            lo[(size_t)row * DD + c + j] = __float2bfloat16(y[j] - __bfloat162float(h));
        }
    }
}

// ================= weight transpose + split =================
__global__ void transpose_split_kernel(const float* __restrict__ W,
                                       __nv_bfloat16* __restrict__ Thi,
                                       __nv_bfloat16* __restrict__ Tlo,
                                       int K, int N) {
    __shared__ float t[32][33];
    int n0 = blockIdx.x * 32, k0 = blockIdx.y * 32;
    int tx = threadIdx.x, ty = threadIdx.y;
#pragma unroll
    for (int r = 0; r < 4; r++) {
        int k = ty + r * 8;
        t[k][tx] = W[(size_t)(k0 + k) * N + n0 + tx];
    }
    __syncthreads();
#pragma unroll
    for (int r = 0; r < 4; r++) {
        int n = ty + r * 8;
        float v = t[tx][n];
        __nv_bfloat16 h = __float2bfloat16(v);
        Thi[(size_t)(n0 + n) * K + k0 + tx] = h;
        Tlo[(size_t)(n0 + n) * K + k0 + tx] = __float2bfloat16(v - __bfloat162float(h));
    }
}

// ================= mma.sync bf16x3 GEMM: 128x256 tile, 512 threads, 4-stage =================
#define TM 128
#define TN 256
#define KC 32
#define AHI_OFF 0
#define ALO_OFF 8192
#define BHI_OFF 16384
#define BLO_OFF 32768
#define STG_BYTES 49152
#define GEMM_SMEM (4 * STG_BYTES)

__global__ void __launch_bounds__(512, 1) gemm_mma3_kernel(
    const __nv_bfloat16* __restrict__ Ahi, const __nv_bfloat16* __restrict__ Alo,
    const __nv_bfloat16* __restrict__ Bhi, const __nv_bfloat16* __restrict__ Blo,
    const float* __restrict__ bias, const float* __restrict__ R,
    float* __restrict__ C, int M, int N, int K)
{
    extern __shared__ char sm[];
    const int tid = threadIdx.x;
    const int lane = tid & 31;
    const int wid = tid >> 5;
    const int wm = wid & 3;
    const int wn = wid >> 2;
    const int bm = blockIdx.x * TM;
    const int bn = blockIdx.y * TN;
    const uint32_t smb = smem_u32(sm);

    const int rowA_base = wm * 32 + (lane & 15);
    const int rowB_base = wn * 64 + (lane & 7) + ((lane >> 4) << 3);
    const uint32_t xorw = (uint32_t)((lane & 6) << 3);

    float acc[2][8][4];
#pragma unroll
    for (int i = 0; i < 2; i++)
#pragma unroll
        for (int j = 0; j < 8; j++)
#pragma unroll
            for (int q = 0; q < 4; q++) acc[i][j][q] = 0.f;

    auto issue_chunk = [&](int k0, int stg) {
        const uint32_t sbase = smb + stg * STG_BYTES;
#pragma unroll
        for (int i = 0; i < 6; i++) {
            int u = tid + (i << 9);
            const __nv_bfloat16* src;
            uint32_t roff;
            int row;
            if (u < 512)       { row = u >> 2;          src = Ahi + (size_t)(bm + row) * K; roff = AHI_OFF; }
            else if (u < 1024) { row = (u - 512) >> 2;  src = Alo + (size_t)(bm + row) * K; roff = ALO_OFF; }
            else if (u < 2048) { row = (u - 1024) >> 2; src = Bhi + (size_t)(bn + row) * K; roff = BHI_OFF; }
            else               { row = (u - 2048) >> 2; src = Blo + (size_t)(bn + row) * K; roff = BLO_OFF; }
            int seg = u & 3;
            uint32_t dst = sbase + roff + (uint32_t)(row * 64) +
                           (((uint32_t)(seg * 16)) ^ ((uint32_t)((row & 6) << 3)));
            CP_ASYNC16(dst, src + k0 + seg * 8);
        }
        CP_COMMIT();
    };

    const int NC = K / KC;
    issue_chunk(0, 0);
    issue_chunk(KC, 1);
    issue_chunk(2 * KC, 2);

    for (int c = 0; c < NC; ++c) {
        CP_WAIT2();
        __syncthreads();
        // issue next chunk BEFORE compute: stage (c+3)%4 was consumed at iter c-1
        if (c + 3 < NC) issue_chunk((c + 3) * KC, (c + 3) & 3);
        else CP_COMMIT();  // empty group keeps wait accounting uniform

        const uint32_t stg = smb + (uint32_t)((c & 3) * STG_BYTES);

#pragma unroll
        for (int kk = 0; kk < 2; kk++) {
            const uint32_t cbA = ((uint32_t)(kk * 32 + ((lane >> 4) << 4))) ^ xorw;
            const uint32_t cbB = ((uint32_t)(kk * 32 + (((lane >> 3) & 1) << 4))) ^ xorw;

            uint32_t ah[2][4], bh4[4][4], fa[2][4], fb[4][4];
#pragma unroll
            for (int mt = 0; mt < 2; mt++)
                LDSM4(ah[mt], stg + AHI_OFF + (uint32_t)((rowA_base + mt * 16) * 64) + cbA);
#pragma unroll
            for (int bt = 0; bt < 4; bt++)
                LDSM4(bh4[bt], stg + BHI_OFF + (uint32_t)((rowB_base + bt * 16) * 64) + cbB);
            // hi x hi
#pragma unroll
            for (int mt = 0; mt < 2; mt++)
#pragma unroll
                for (int nt = 0; nt < 8; nt++) {
                    const uint32_t* b = bh4[nt >> 1];
                    if (nt & 1) MMA_BF16(acc[mt][nt], ah[mt], b[2], b[3]);
                    else        MMA_BF16(acc[mt][nt], ah[mt], b[0], b[1]);
                }
            // lo x hi (reuse bh4)
#pragma unroll
            for (int mt = 0; mt < 2; mt++)
                LDSM4(fa[mt], stg + ALO_OFF + (uint32_t)((rowA_base + mt * 16) * 64) + cbA);
#pragma unroll
            for (int mt = 0; mt < 2; mt++)
#pragma unroll
                for (int nt = 0; nt < 8; nt++) {
                    const uint32_t* b = bh4[nt >> 1];
                    if (nt & 1) MMA_BF16(acc[mt][nt], fa[mt], b[2], b[3]);
                    else        MMA_BF16(acc[mt][nt], fa[mt], b[0], b[1]);
                }
            // hi x lo
#pragma unroll
            for (int bt = 0; bt < 4; bt++)
                LDSM4(fb[bt], stg + BLO_OFF + (uint32_t)((rowB_base + bt * 16) * 64) + cbB);
#pragma unroll
            for (int mt = 0; mt < 2; mt++)
#pragma unroll
                for (int nt = 0; nt < 8; nt++) {
                    const uint32_t* b = fb[nt >> 1];
                    if (nt & 1) MMA_BF16(acc[mt][nt], ah[mt], b[2], b[3]);
                    else        MMA_BF16(acc[mt][nt], ah[mt], b[0], b[1]);
                }
        }
    }

    // ---- epilogue ----
#pragma unroll
    for (int mt = 0; mt < 2; mt++) {
        const int m = bm + wm * 32 + mt * 16 + (lane >> 2);
#pragma unroll
        for (int nt = 0; nt < 8; nt++) {
            const int n = bn + wn * 64 + nt * 8 + ((lane & 3) << 1);
            float2 b2 = *(const float2*)(bias + n);
            float2 o0, o1;
            o0.x = acc[mt][nt][0] + b2.x;
            o0.y = acc[mt][nt][1] + b2.y;
            o1.x = acc[mt][nt][2] + b2.x;
            o1.y = acc[mt][nt][3] + b2.y;
            if (R) {
                float2 r0 = *(const float2*)(R + (size_t)m * N + n);
                float2 r1 = *(const float2*)(R + (size_t)(m + 8) * N + n);
                o0.x += r0.x; o0.y += r0.y;
                o1.x += r1.x; o1.y += r1.y;
            }
            *(float2*)(C + (size_t)m * N + n) = o0;
            *(float2*)(C + (size_t)(m + 8) * N + n) = o1;
        }
    }
}

// ================= RoPE: qkv fp32 -> split bf16 q,k in [B,H,L,HD] =================
__global__ void rope_apply_split_kernel() {
    int idx = blockIdx.x * blockDim.x + threadIdx.x;
    if (idx >= BB * LL * HH * 64) return;
    int d = idx & 63;
    int h = (idx >> 6) & (HH - 1);
    int bl = idx >> 10;
    int b = bl >> 11;
    int l = bl & (LL - 1);
    float c = g_cos[l * 64 + d];
    float s = g_sin[l * 64 + d];
    size_t src = (size_t)bl * D3 + h * HD + d;
    size_t dst = ((size_t)(b * HH + h) * LL + l) * HD + d;

    float q1 = g_qkv[src], q2 = g_qkv[src + 64];
    float qa = q1 * c - q2 * s;
    float qb = q2 * c + q1 * s;
    __nv_bfloat16 t;
    t = __float2bfloat16(qa); g_qh[dst] = t;      g_ql[dst] = __float2bfloat16(qa - __bfloat162float(t));
    t = __float2bfloat16(qb); g_qh[dst + 64] = t; g_ql[dst + 64] = __float2bfloat16(qb - __bfloat162float(t));

    size_t ks = src + DD;
    float k1 = g_qkv[ks], k2 = g_qkv[ks + 64];
    float ka = k1 * c - k2 * s;
    float kb = k2 * c + k1 * s;
    t = __float2bfloat16(ka); g_kh[dst] = t;      g_kl[dst] = __float2bfloat16(ka - __bfloat162float(t));
    t = __float2bfloat16(kb); g_kh[dst + 64] = t; g_kl[dst + 64] = __float2bfloat16(kb - __bfloat162float(t));
}

// ================= V transpose + split =================
__global__ void v_transpose_split_kernel() {
    __shared__ float t[32][33];
    int l0 = blockIdx.x * 32, d0 = blockIdx.y * 32, bh = blockIdx.z;
    int b = bh >> 4, h = bh & 15;
    int tx = threadIdx.x, ty = threadIdx.y;
#pragma unroll
    for (int r = 0; r < 4; r++) {
        int l = ty + r * 8;
        t[l][tx] = g_qkv[(size_t)(b * LL + l0 + l) * D3 + 2 * DD + h * HD + d0 + tx];
    }
    __syncthreads();
#pragma unroll
    for (int r = 0; r < 4; r++) {
        int d = ty + r * 8;
        float v = t[tx][d];
        __nv_bfloat16 hv = __float2bfloat16(v);
        size_t dst = ((size_t)bh * HD + d0 + d) * LL + l0 + tx;
        g_vth[dst] = hv;
        g_vtl[dst] = __float2bfloat16(v - __bfloat162float(hv));
    }
}

// ================= attention scores (bf16x3 MMA, 4-stage) =================
#define ATT_STG 32768
#define ATT_SMEM (4 * ATT_STG)

__global__ void __launch_bounds__(256, 1) attn_scores_mma_kernel() {
    extern __shared__ char sm[];
    const int jb = blockIdx.x, ib = blockIdx.y, bh = blockIdx.z;
    if (jb > ib) return;
    const int tid = threadIdx.x, lane = tid & 31, wid = tid >> 5;
    const int wm = wid & 3, wn = wid >> 2;
    const uint32_t smb = smem_u32(sm);

    const __nv_bfloat16* Qh = g_qh + ((size_t)bh * LL + ib * 128) * HD;
    const __nv_bfloat16* Ql = g_ql + ((size_t)bh * LL + ib * 128) * HD;
    const __nv_bfloat16* Kh = g_kh + ((size_t)bh * LL + jb * 128) * HD;
    const __nv_bfloat16* Kl = g_kl + ((size_t)bh * LL + jb * 128) * HD;

    const int rowA_base = wm * 32 + (lane & 15);
    const int rowB_base = wn * 64 + (lane & 7) + ((lane >> 4) << 3);
    const uint32_t xorw = (uint32_t)((lane & 6) << 3);

    float acc[2][8][4];
#pragma unroll
    for (int i = 0; i < 2; i++)
#pragma unroll
        for (int j = 0; j < 8; j++)
#pragma unroll
            for (int q = 0; q < 4; q++) acc[i][j][q] = 0.f;

    auto issue = [&](int c, int stg) {
        const uint32_t sb = smb + (uint32_t)(stg * ATT_STG);
        const int k0 = c * 32;
#pragma unroll
        for (int i = 0; i < 8; i++) {
            int u = tid + (i << 8);
            int row = (u >> 2) & 127;
            int seg = u & 3;
            const __nv_bfloat16* src = (u < 512) ? Qh : (u < 1024) ? Ql : (u < 1536) ? Kh : Kl;
            uint32_t roff = (uint32_t)(u >> 9) * 8192;
            uint32_t dst = sb + roff + (uint32_t)(row * 64) +
                           (((uint32_t)(seg * 16)) ^ ((uint32_t)((row & 6) << 3)));
            CP_ASYNC16(dst, src + (size_t)row * HD + k0 + seg * 8);
        }
        CP_COMMIT();
    };

    issue(0, 0);
    issue(1, 1);
    issue(2, 2);
#pragma unroll 1
    for (int c = 0; c < 4; c++) {
        CP_WAIT2();
        __syncthreads();
        if (c + 3 < 4) issue(c + 3, (c + 3) & 3);
        else CP_COMMIT();
        const uint32_t stg = smb + (uint32_t)((c & 3) * ATT_STG);
#pragma unroll
        for (int kk = 0; kk < 2; kk++) {
            const uint32_t cbA = ((uint32_t)(kk * 32 + ((lane >> 4) << 4))) ^ xorw;
            const uint32_t cbB = ((uint32_t)(kk * 32 + (((lane >> 3) & 1) << 4))) ^ xorw;
            uint32_t ah[2][4], bh4[4][4], fb[4][4], fa[2][4];
#pragma unroll
            for (int mt = 0; mt < 2; mt++)
                LDSM4(ah[mt], stg + 0 + (uint32_t)((rowA_base + mt * 16) * 64) + cbA);
#pragma unroll
            for (int bt = 0; bt < 4; bt++)
                LDSM4(bh4[bt], stg + 16384 + (uint32_t)((rowB_base + bt * 16) * 64) + cbB);
#pragma unroll
            for (int mt = 0; mt < 2; mt++)
#pragma unroll
                for (int nt = 0; nt < 8; nt++) {
                    const uint32_t* b = bh4[nt >> 1];
                    if (nt & 1) MMA_BF16(acc[mt][nt], ah[mt], b[2], b[3]);
                    else        MMA_BF16(acc[mt][nt], ah[mt], b[0], b[1]);
                }
#pragma unroll
            for (int mt = 0; mt < 2; mt++)
                LDSM4(fa[mt], stg + 8192 + (uint32_t)((rowA_base + mt * 16) * 64) + cbA);
#pragma unroll
            for (int mt = 0; mt < 2; mt++)
#pragma unroll
                for (int nt = 0; nt < 8; nt++) {
                    const uint32_t* b = bh4[nt >> 1];
                    if (nt & 1) MMA_BF16(acc[mt][nt], fa[mt], b[2], b[3]);
                    else        MMA_BF16(acc[mt][nt], fa[mt], b[0], b[1]);
                }
#pragma unroll
            for (int bt = 0; bt < 4; bt++)
                LDSM4(fb[bt], stg + 24576 + (uint32_t)((rowB_base + bt * 16) * 64) + cbB);
#pragma unroll
            for (int mt = 0; mt < 2; mt++)
#pragma unroll
                for (int nt = 0; nt < 8; nt++) {
                    const uint32_t* b = fb[nt >> 1];
                    if (nt & 1) MMA_BF16(acc[mt][nt], ah[mt], b[2], b[3]);
                    else        MMA_BF16(acc[mt][nt], ah[mt], b[0], b[1]);
                }
        }
    }

    const float scale = 0.08838834764831845f;
#pragma unroll
    for (int mt = 0; mt < 2; mt++) {
        const int i0 = ib * 128 + wm * 32 + mt * 16 + (lane >> 2);
#pragma unroll
        for (int nt = 0; nt < 8; nt++) {
            const int j0 = jb * 128 + wn * 64 + nt * 8 + ((lane & 3) << 1);
            float2 o0, o1;
            o0.x = (j0     <= i0)     ? acc[mt][nt][0] * scale : -1e30f;
            o0.y = (j0 + 1 <= i0)     ? acc[mt][nt][1] * scale : -1e30f;
            o1.x = (j0     <= i0 + 8) ? acc[mt][nt][2] * scale : -1e30f;
            o1.y = (j0 + 1 <= i0 + 8) ? acc[mt][nt][3] * scale : -1e30f;
            *(float2*)(g_s + ((size_t)bh * LL + i0) * LL + j0) = o0;
            *(float2*)(g_s + ((size_t)bh * LL + i0 + 8) * LL + j0) = o1;
        }
    }
}

// ================= row softmax -> split bf16 P =================
__global__ void softmax_kernel() {
    int r = blockIdx.x;
    int i = r & (LL - 1);
    int len = ((i >> 6) + 1) << 6;
    int len2 = ((i >> 7) + 1) << 7;
    float* p = g_s + (size_t)r * LL;
    __nv_bfloat16* ph = g_ph + (size_t)r * LL;
    __nv_bfloat16* pl = g_pl + (size_t)r * LL;
    __shared__ float red[128];

    float m = -1e30f;
    for (int c = threadIdx.x; c < len; c += 128) m = fmaxf(m, p[c]);
    red[threadIdx.x] = m;
    __syncthreads();
    for (int s = 64; s > 0; s >>= 1) {
        if (threadIdx.x < s) red[threadIdx.x] = fmaxf(red[threadIdx.x], red[threadIdx.x + s]);
        __syncthreads();
    }
    m = red[0];
    __syncthreads();

    float sum = 0.f;
    for (int c = threadIdx.x; c < len; c += 128) {
        float e = expf(p[c] - m);
        p[c] = e;
        sum += e;
    }
    red[threadIdx.x] = sum;
    __syncthreads();
    for (int s = 64; s > 0; s >>= 1) {
        if (threadIdx.x < s) red[threadIdx.x] += red[threadIdx.x + s];
        __syncthreads();
    }
    float inv = 1.f / red[0];
    for (int c = threadIdx.x; c < len; c += 128) {
        float v = p[c] * inv;
        __nv_bfloat16 hv = __float2bfloat16(v);
        ph[c] = hv;
        pl[c] = __float2bfloat16(v - __bfloat162float(hv));
    }
    for (int c = len + threadIdx.x; c < len2; c += 128) {
        ph[c] = __float2bfloat16(0.f);
        pl[c] = __float2bfloat16(0.f);
    }
}

// ================= O = P @ V (bf16x3 MMA, 4-stage) -> split o =================
__global__ void __launch_bounds__(256, 1) attn_pv_mma_kernel() {
    extern __shared__ char sm[];
    const int ib = blockIdx.x, bh = blockIdx.y;
    const int b = bh >> 4, h = bh & 15;
    const int tid = threadIdx.x, lane = tid & 31, wid = tid >> 5;
    const int wm = wid & 3, wn = wid >> 2;
    const uint32_t smb = smem_u32(sm);

    const __nv_bfloat16* Ph = g_ph + ((size_t)bh * LL + ib * 128) * LL;
    const __nv_bfloat16* Pl = g_pl + ((size_t)bh * LL + ib * 128) * LL;
    const __nv_bfloat16* Vh = g_vth + (size_t)bh * HD * LL;
    const __nv_bfloat16* Vl = g_vtl + (size_t)bh * HD * LL;

    const int rowA_base = wm * 32 + (lane & 15);
    const int rowB_base = wn * 64 + (lane & 7) + ((lane >> 4) << 3);
    const uint32_t xorw = (uint32_t)((lane & 6) << 3);

    float acc[2][8][4];
#pragma unroll
    for (int i = 0; i < 2; i++)
#pragma unroll
        for (int j = 0; j < 8; j++)
#pragma unroll
            for (int q = 0; q < 4; q++) acc[i][j][q] = 0.f;

    auto issue = [&](int c, int stg) {
        const uint32_t sb = smb + (uint32_t)(stg * ATT_STG);
        const int j0 = c * 32;
#pragma unroll
        for (int i = 0; i < 8; i++) {
            int u = tid + (i << 8);
            int row = (u >> 2) & 127;
            int seg = u & 3;
            const __nv_bfloat16* src = (u < 512) ? Ph : (u < 1024) ? Pl : (u < 1536) ? Vh : Vl;
            uint32_t roff = (uint32_t)(u >> 9) * 8192;
            uint32_t dst = sb + roff + (uint32_t)(row * 64) +
                           (((uint32_t)(seg * 16)) ^ ((uint32_t)((row & 6) << 3)));
            CP_ASYNC16(dst, src + (size_t)row * LL + j0 + seg * 8);
        }
        CP_COMMIT();
    };

    const int NC = (ib + 1) * 4;
    issue(0, 0);
    issue(1, 1);
    issue(2, 2);
#pragma unroll 1
    for (int c = 0; c < NC; c++) {
        CP_WAIT2();
        __syncthreads();
        if (c + 3 < NC) issue(c + 3, (c + 3) & 3);
        else CP_COMMIT();
        const uint32_t stg = smb + (uint32_t)((c & 3) * ATT_STG);
#pragma unroll
        for (int kk = 0; kk < 2; kk++) {
            const uint32_t cbA = ((uint32_t)(kk * 32 + ((lane >> 4) << 4))) ^ xorw;
            const uint32_t cbB = ((uint32_t)(kk * 32 + (((lane >> 3) & 1) << 4))) ^ xorw;
            uint32_t ah[2][4], bh4[4][4], fb[4][4], fa[2][4];
#pragma unroll
            for (int mt = 0; mt < 2; mt++)
                LDSM4(ah[mt], stg + 0 + (uint32_t)((rowA_base + mt * 16) * 64) + cbA);
#pragma unroll
            for (int bt = 0; bt < 4; bt++)
                LDSM4(bh4[bt], stg + 16384 + (uint32_t)((rowB_base + bt * 16) * 64) + cbB);
#pragma unroll
            for (int mt = 0; mt < 2; mt++)
#pragma unroll
                for (int nt = 0; nt < 8; nt++) {
                    const uint32_t* bb = bh4[nt >> 1];
                    if (nt & 1) MMA_BF16(acc[mt][nt], ah[mt], bb[2], bb[3]);
                    else        MMA_BF16(acc[mt][nt], ah[mt], bb[0], bb[1]);
                }
#pragma unroll
            for (int mt = 0; mt < 2; mt++)
                LDSM4(fa[mt], stg + 8192 + (uint32_t)((rowA_base + mt * 16) * 64) + cbA);
#pragma unroll
            for (int mt = 0; mt < 2; mt++)
#pragma unroll
                for (int nt = 0; nt < 8; nt++) {
                    const uint32_t* bb = bh4[nt >> 1];
                    if (nt & 1) MMA_BF16(acc[mt][nt], fa[mt], bb[2], bb[3]);
                    else        MMA_BF16(acc[mt][nt], fa[mt], bb[0], bb[1]);
                }
#pragma unroll
            for (int bt = 0; bt < 4; bt++)
                LDSM4(fb[bt], stg + 24576 + (uint32_t)((rowB_base + bt * 16) * 64) + cbB);
#pragma unroll
            for (int mt = 0; mt < 2; mt++)
#pragma unroll
                for (int nt = 0; nt < 8; nt++) {
                    const uint32_t* bb = fb[nt >> 1];
                    if (nt & 1) MMA_BF16(acc[mt][nt], ah[mt], bb[2], bb[3]);
                    else        MMA_BF16(acc[mt][nt], ah[mt], bb[0], bb[1]);
                }
        }
    }

#pragma unroll
    for (int mt = 0; mt < 2; mt++) {
        const int qi = ib * 128 + wm * 32 + mt * 16 + (lane >> 2);
#pragma unroll
        for (int nt = 0; nt < 8; nt++) {
            const int d = wn * 64 + nt * 8 + ((lane & 3) << 1);
            size_t base0 = (size_t)(b * LL + qi) * DD + h * HD + d;
            size_t base1 = (size_t)(b * LL + qi + 8) * DD + h * HD + d;
            float v0 = acc[mt][nt][0], v1 = acc[mt][nt][1];
            float v2 = acc[mt][nt][2], v3 = acc[mt][nt][3];
            __nv_bfloat16 h0 = __float2bfloat16(v0), h1 = __float2bfloat16(v1);
            __nv_bfloat16 h2 = __float2bfloat16(v2), h3 = __float2bfloat16(v3);
            *(__nv_bfloat162*)(g_ah + base0) = __halves2bfloat162(h0, h1);
            *(__nv_bfloat162*)(g_ah + base1) = __halves2bfloat162(h2, h3);
            *(__nv_bfloat162*)(g_al + base0) = __halves2bfloat162(
                __float2bfloat16(v0 - __bfloat162float(h0)),
                __float2bfloat16(v1 - __bfloat162float(h1)));
            *(__nv_bfloat162*)(g_al + base1) = __halves2bfloat162(
                __float2bfloat16(v2 - __bfloat162float(h2)),
                __float2bfloat16(v3 - __bfloat162float(h3)));
        }
    }
}

// ================= SwiGLU -> split bf16 =================
__global__ void swiglu_split_kernel() {
    size_t idx = (size_t)blockIdx.x * blockDim.x + threadIdx.x;
    if (idx >= (size_t)MROWS * D4) return;
    size_t row = idx >> 13;
    int col = (int)(idx & (D4 - 1));
    float gv = g_p[row * D8 + col];
    float vv = g_p[row * D8 + D4 + col];
    float r = gv / (1.f + expf(-gv)) * vv;
    __nv_bfloat16 hv = __float2bfloat16(r);
    g_ah[idx] = hv;
    g_al[idx] = __float2bfloat16(r - __bfloat162float(hv));
}

// ================= launch =================
extern "C" void kernel_launch(void* const* d_in, const int* in_sizes, int n_in,
                              void* d_out, int out_size) {
    const float* x    = (const float*)d_in[0];
    const float* Wqkv = (const float*)d_in[1];
    const float* bqkv = (const float*)d_in[2];
    const float* Wo   = (const float*)d_in[3];
    const float* bo   = (const float*)d_in[4];
    const float* g1   = (const float*)d_in[5];
    const float* g2   = (const float*)d_in[6];
    const float* Wp   = (const float*)d_in[7];
    const float* bp   = (const float*)d_in[8];
    const float* Wff  = (const float*)d_in[9];
    const float* bff  = (const float*)d_in[10];
    float* out = (float*)d_out;

    __nv_bfloat16 *ah, *al, *wqh, *wql, *woh, *wol, *wph, *wpl, *wfh, *wfl;
    float *qkv, *x1, *p;
    cudaGetSymbolAddress((void**)&ah,  g_ah);
    cudaGetSymbolAddress((void**)&al,  g_al);
    cudaGetSymbolAddress((void**)&wqh, g_WqkvT_hi);
    cudaGetSymbolAddress((void**)&wql, g_WqkvT_lo);
    cudaGetSymbolAddress((void**)&woh, g_WoT_hi);
    cudaGetSymbolAddress((void**)&wol, g_WoT_lo);
    cudaGetSymbolAddress((void**)&wph, g_WpT_hi);
    cudaGetSymbolAddress((void**)&wpl, g_WpT_lo);
    cudaGetSymbolAddress((void**)&wfh, g_WffT_hi);
    cudaGetSymbolAddress((void**)&wfl, g_WffT_lo);
    cudaGetSymbolAddress((void**)&qkv, g_qkv);
    cudaGetSymbolAddress((void**)&x1,  g_x1);
    cudaGetSymbolAddress((void**)&p,   g_p);

    cudaFuncSetAttribute(gemm_mma3_kernel,
                         cudaFuncAttributeMaxDynamicSharedMemorySize, GEMM_SMEM);
    cudaFuncSetAttribute(attn_scores_mma_kernel,
                         cudaFuncAttributeMaxDynamicSharedMemorySize, ATT_SMEM);
    cudaFuncSetAttribute(attn_pv_mma_kernel,
                         cudaFuncAttributeMaxDynamicSharedMemorySize, ATT_SMEM);

    dim3 tb(32, 8);

    // 1) h = rms(x, g1), split
    rmsnorm_split_kernel<<<MROWS, 256>>>(x, g1, ah, al);
    // 2) Wqkv transpose/split
    transpose_split_kernel<<<dim3(D3 / 32, DD / 32), tb>>>(Wqkv, wqh, wql, DD, D3);
    // 3) RoPE tables
    rope_table_kernel<<<LL, 64>>>();
    // 4) qkv = h @ Wqkv + bqkv   (launch #4 — profiled)
    gemm_mma3_kernel<<<dim3(MROWS / TM, D3 / TN), 512, GEMM_SMEM>>>(
        ah, al, wqh, wql, bqkv, nullptr, qkv, MROWS, D3, DD);
    // 5) RoPE apply + split q,k
    {
        int total = BB * LL * HH * 64;
        rope_apply_split_kernel<<<(total + 255) / 256, 256>>>();
    }
    // 6) V transpose + split
    v_transpose_split_kernel<<<dim3(LL / 32, HD / 32, BB * HH), tb>>>();
    // 7) scores
    attn_scores_mma_kernel<<<dim3(LL / 128, LL / 128, BB * HH), 256, ATT_SMEM>>>();
    // 8) softmax -> split P
    softmax_kernel<<<BB * HH * LL, 128>>>();
    // 9) O = P @ V
    attn_pv_mma_kernel<<<dim3(LL / 128, BB * HH), 256, ATT_SMEM>>>();
    // 10) Wo transpose/split
    transpose_split_kernel<<<dim3(DD / 32, DD / 32), tb>>>(Wo, woh, wol, DD, DD);
    // 11) x1 = o @ Wo + bo + x
    gemm_mma3_kernel<<<dim3(MROWS / TM, DD / TN), 512, GEMM_SMEM>>>(
        ah, al, woh, wol, bo, x, x1, MROWS, DD, DD);
    // 12) h2 = rms(x1, g2), split
    rmsnorm_split_kernel<<<MROWS, 256>>>(x1, g2, ah, al);
    // 13) Wp transpose/split
    transpose_split_kernel<<<dim3(D8 / 32, DD / 32), tb>>>(Wp, wph, wpl, DD, D8);
    // 14) p = h2 @ Wp + bp
    gemm_mma3_kernel<<<dim3(MROWS / TM, D8 / TN), 512, GEMM_SMEM>>>(
        ah, al, wph, wpl, bp, nullptr, p, MROWS, D8, DD);
    // 15) ffh = silu(gate) * value, split
    {
        size_t total = (size_t)MROWS * D4;
        swiglu_split_kernel<<<(unsigned)((total + 255) / 256), 256>>>();
    }
    // 16) Wff transpose/split
    transpose_split_kernel<<<dim3(DD / 32, D4 / 32), tb>>>(Wff, wfh, wfl, D4, DD);
    // 17) out = ffh @ Wff + bff + x1
    gemm_mma3_kernel<<<dim3(MROWS / TM, DD / TN), 512, GEMM_SMEM>>>(
        ah, al, wfh, wfl, bff, x1, out, MROWS, DD, D4);
}

// round 7
// speedup vs baseline: 1.1296x; 1.0360x over previous
#include <cuda_runtime.h>
#include <cuda_bf16.h>
#include <math.h>
#include <stdint.h>

// Problem constants
#define BB 2
#define LL 2048
#define DD 2048
#define HH 16
#define HD 128
#define MROWS (BB * LL)        // 4096
#define D3 (3 * DD)            // 6144
#define D8 (8 * DD)            // 16384
#define D4 (4 * DD)            // 8192

// ---------------- scratch ----------------
__device__ float g_qkv[(size_t)MROWS * D3];
__device__ float g_s  [(size_t)BB * HH * LL * LL];
__device__ float g_x1 [(size_t)MROWS * DD];
__device__ float g_p  [(size_t)MROWS * D8];
__device__ float g_cos[LL * 64];
__device__ float g_sin[LL * 64];

__device__ __align__(16) __nv_bfloat16 g_ah[(size_t)MROWS * D4];
__device__ __align__(16) __nv_bfloat16 g_al[(size_t)MROWS * D4];

__device__ __align__(16) __nv_bfloat16 g_qh[(size_t)BB * HH * LL * HD];
__device__ __align__(16) __nv_bfloat16 g_ql[(size_t)BB * HH * LL * HD];
__device__ __align__(16) __nv_bfloat16 g_kh[(size_t)BB * HH * LL * HD];
__device__ __align__(16) __nv_bfloat16 g_kl[(size_t)BB * HH * LL * HD];
__device__ __align__(16) __nv_bfloat16 g_vth[(size_t)BB * HH * HD * LL];
__device__ __align__(16) __nv_bfloat16 g_vtl[(size_t)BB * HH * HD * LL];
__device__ __align__(16) __nv_bfloat16 g_ph[(size_t)BB * HH * LL * LL];
__device__ __align__(16) __nv_bfloat16 g_pl[(size_t)BB * HH * LL * LL];

__device__ __align__(16) __nv_bfloat16 g_WqkvT_hi[(size_t)D3 * DD];
__device__ __align__(16) __nv_bfloat16 g_WqkvT_lo[(size_t)D3 * DD];
__device__ __align__(16) __nv_bfloat16 g_WoT_hi[(size_t)DD * DD];
__device__ __align__(16) __nv_bfloat16 g_WoT_lo[(size_t)DD * DD];
__device__ __align__(16) __nv_bfloat16 g_WpT_hi[(size_t)D8 * DD];
__device__ __align__(16) __nv_bfloat16 g_WpT_lo[(size_t)D8 * DD];
__device__ __align__(16) __nv_bfloat16 g_WffT_hi[(size_t)DD * D4];
__device__ __align__(16) __nv_bfloat16 g_WffT_lo[(size_t)DD * D4];

// ================= helpers =================
__device__ __forceinline__ uint32_t smem_u32(const void* p) {
    uint32_t a;
    asm("{ .reg .u64 t; cvta.to.shared.u64 t, %1; cvt.u32.u64 %0, t; }" : "=r"(a) : "l"(p));
    return a;
}

#define CP_ASYNC16(dst, src) \
    asm volatile("cp.async.cg.shared.global [%0], [%1], 16;" :: "r"(dst), "l"(src) : "memory")
#define CP_COMMIT() asm volatile("cp.async.commit_group;" ::: "memory")
#define CP_WAIT1()  asm volatile("cp.async.wait_group 1;" ::: "memory")

#define LDSM4(r, addr) \
    asm volatile("ldmatrix.sync.aligned.m8n8.x4.shared.b16 {%0,%1,%2,%3}, [%4];" \
        : "=r"((r)[0]), "=r"((r)[1]), "=r"((r)[2]), "=r"((r)[3]) : "r"(addr))

#define MMA_BF16(d, a, b0, b1) \
    asm volatile("mma.sync.aligned.m16n8k16.row.col.f32.bf16.bf16.f32 " \
        "{%0,%1,%2,%3}, {%4,%5,%6,%7}, {%8,%9}, {%0,%1,%2,%3};" \
        : "+f"((d)[0]), "+f"((d)[1]), "+f"((d)[2]), "+f"((d)[3]) \
        : "r"((a)[0]), "r"((a)[1]), "r"((a)[2]), "r"((a)[3]), "r"(b0), "r"(b1))

// ================= RoPE tables =================
__global__ void rope_table_kernel() {
    int p = blockIdx.x, i = threadIdx.x;
    double inv_freq = pow(10000.0, -(double)(2 * i) / (double)HD);
    double ang = (double)p * inv_freq;
    g_cos[p * 64 + i] = (float)cos(ang);
    g_sin[p * 64 + i] = (float)sin(ang);
}

// ================= RMSNorm -> split bf16 hi/lo =================
__global__ void rmsnorm_split_kernel(const float* __restrict__ x,
                                     const float* __restrict__ g,
                                     __nv_bfloat16* __restrict__ hi,
                                     __nv_bfloat16* __restrict__ lo) {
    int row = blockIdx.x;
    const float* xr = x + (size_t)row * DD;
    float ss = 0.f;
    for (int c = threadIdx.x * 4; c < DD; c += blockDim.x * 4) {
        float4 v = *(const float4*)(xr + c);
        ss += v.x * v.x + v.y * v.y + v.z * v.z + v.w * v.w;
    }
    __shared__ float red[256];
    red[threadIdx.x] = ss;
    __syncthreads();
    for (int s = blockDim.x / 2; s > 0; s >>= 1) {
        if (threadIdx.x < s) red[threadIdx.x] += red[threadIdx.x + s];
        __syncthreads();
    }
    float scale = rsqrtf(red[0] / (float)DD + 1e-8f);
    for (int c = threadIdx.x * 4; c < DD; c += blockDim.x * 4) {
        float4 v = *(const float4*)(xr + c);
        float4 gv = *(const float4*)(g + c);
        float y[4] = {v.x * scale * gv.x, v.y * scale * gv.y,
                      v.z * scale * gv.z, v.w * scale * gv.w};
#pragma unroll
        for (int j = 0; j < 4; j++) {
            __nv_bfloat16 h = __float2bfloat16(y[j]);
            hi[(size_t)row * DD + c + j] = h;
            lo[(size_t)row * DD + c + j] = __float2bfloat16(y[j] - __bfloat162float(h));
        }
    }
}

// ================= weight transpose + split =================
__global__ void transpose_split_kernel(const float* __restrict__ W,
                                       __nv_bfloat16* __restrict__ Thi,
                                       __nv_bfloat16* __restrict__ Tlo,
                                       int K, int N) {
    __shared__ float t[32][33];
    int n0 = blockIdx.x * 32, k0 = blockIdx.y * 32;
    int tx = threadIdx.x, ty = threadIdx.y;
#pragma unroll
    for (int r = 0; r < 4; r++) {
        int k = ty + r * 8;
        t[k][tx] = W[(size_t)(k0 + k) * N + n0 + tx];
    }
    __syncthreads();
#pragma unroll
    for (int r = 0; r < 4; r++) {
        int n = ty + r * 8;
        float v = t[tx][n];
        __nv_bfloat16 h = __float2bfloat16(v);
        Thi[(size_t)(n0 + n) * K + k0 + tx] = h;
        Tlo[(size_t)(n0 + n) * K + k0 + tx] = __float2bfloat16(v - __bfloat162float(h));
    }
}

// ====== mma.sync bf16x3 GEMM: 128x128 tile, 256 threads, 3-stage, 2 CTAs/SM ======
#define TM 128
#define TN 128
#define KC 32
#define AHI_OFF 0
#define ALO_OFF 8192
#define BHI_OFF 16384
#define BLO_OFF 24576
#define STG_BYTES 32768
#define GEMM_SMEM (3 * STG_BYTES)

__global__ void __launch_bounds__(256, 2) gemm_mma3_kernel(
    const __nv_bfloat16* __restrict__ Ahi, const __nv_bfloat16* __restrict__ Alo,
    const __nv_bfloat16* __restrict__ Bhi, const __nv_bfloat16* __restrict__ Blo,
    const float* __restrict__ bias, const float* __restrict__ R,
    float* __restrict__ C, int M, int N, int K)
{
    extern __shared__ char sm[];
    const int tid = threadIdx.x;
    const int lane = tid & 31;
    const int wid = tid >> 5;
    const int wm = wid & 3;        // 4 warp-rows of 32
    const int wn = wid >> 2;       // 2 warp-cols of 64
    const int bm = blockIdx.x * TM;
    const int bn = blockIdx.y * TN;
    const uint32_t smb = smem_u32(sm);

    const int rowA_base = wm * 32 + (lane & 15);
    const int rowB_base = wn * 64 + (lane & 7) + ((lane >> 4) << 3);
    const uint32_t xorw = (uint32_t)((lane & 6) << 3);

    float acc[2][8][4];
#pragma unroll
    for (int i = 0; i < 2; i++)
#pragma unroll
        for (int j = 0; j < 8; j++)
#pragma unroll
            for (int q = 0; q < 4; q++) acc[i][j][q] = 0.f;

    // 2048 x 16B per chunk, 8 per thread
    auto issue_chunk = [&](int k0, int stg) {
        const uint32_t sbase = smb + stg * STG_BYTES;
#pragma unroll
        for (int i = 0; i < 8; i++) {
            int u = tid + (i << 8);
            const __nv_bfloat16* src;
            uint32_t roff;
            int row;
            if (u < 512)       { row = u >> 2;          src = Ahi + (size_t)(bm + row) * K; roff = AHI_OFF; }
            else if (u < 1024) { row = (u - 512) >> 2;  src = Alo + (size_t)(bm + row) * K; roff = ALO_OFF; }
            else if (u < 1536) { row = (u - 1024) >> 2; src = Bhi + (size_t)(bn + row) * K; roff = BHI_OFF; }
            else               { row = (u - 1536) >> 2; src = Blo + (size_t)(bn + row) * K; roff = BLO_OFF; }
            int seg = u & 3;
            uint32_t dst = sbase + roff + (uint32_t)(row * 64) +
                           (((uint32_t)(seg * 16)) ^ ((uint32_t)((row & 6) << 3)));
            CP_ASYNC16(dst, src + k0 + seg * 8);
        }
        CP_COMMIT();
    };

    const int NC = K / KC;
    issue_chunk(0, 0);
    issue_chunk(KC, 1);

    for (int c = 0; c < NC; ++c) {
        CP_WAIT1();
        __syncthreads();
        // issue next chunk BEFORE compute: stage (c+2)%3 was consumed at iter c-1
        if (c + 2 < NC) issue_chunk((c + 2) * KC, (c + 2) % 3);
        else CP_COMMIT();  // empty group keeps wait accounting uniform

        const uint32_t stg = smb + (uint32_t)((c % 3) * STG_BYTES);

#pragma unroll
        for (int kk = 0; kk < 2; kk++) {
            const uint32_t cbA = ((uint32_t)(kk * 32 + ((lane >> 4) << 4))) ^ xorw;
            const uint32_t cbB = ((uint32_t)(kk * 32 + (((lane >> 3) & 1) << 4))) ^ xorw;

            uint32_t ah[2][4], bh4[4][4], fa[2][4], fb[4][4];
#pragma unroll
            for (int mt = 0; mt < 2; mt++)
                LDSM4(ah[mt], stg + AHI_OFF + (uint32_t)((rowA_base + mt * 16) * 64) + cbA);
#pragma unroll
            for (int bt = 0; bt < 4; bt++)
                LDSM4(bh4[bt], stg + BHI_OFF + (uint32_t)((rowB_base + bt * 16) * 64) + cbB);
            // hi x hi
#pragma unroll
            for (int mt = 0; mt < 2; mt++)
#pragma unroll
                for (int nt = 0; nt < 8; nt++) {
                    const uint32_t* b = bh4[nt >> 1];
                    if (nt & 1) MMA_BF16(acc[mt][nt], ah[mt], b[2], b[3]);
                    else        MMA_BF16(acc[mt][nt], ah[mt], b[0], b[1]);
                }
            // lo x hi (reuse bh4)
#pragma unroll
            for (int mt = 0; mt < 2; mt++)
                LDSM4(fa[mt], stg + ALO_OFF + (uint32_t)((rowA_base + mt * 16) * 64) + cbA);
#pragma unroll
            for (int mt = 0; mt < 2; mt++)
#pragma unroll
                for (int nt = 0; nt < 8; nt++) {
                    const uint32_t* b = bh4[nt >> 1];
                    if (nt & 1) MMA_BF16(acc[mt][nt], fa[mt], b[2], b[3]);
                    else        MMA_BF16(acc[mt][nt], fa[mt], b[0], b[1]);
                }
            // hi x lo
#pragma unroll
            for (int bt = 0; bt < 4; bt++)
                LDSM4(fb[bt], stg + BLO_OFF + (uint32_t)((rowB_base + bt * 16) * 64) + cbB);
#pragma unroll
            for (int mt = 0; mt < 2; mt++)
#pragma unroll
                for (int nt = 0; nt < 8; nt++) {
                    const uint32_t* b = fb[nt >> 1];
                    if (nt & 1) MMA_BF16(acc[mt][nt], ah[mt], b[2], b[3]);
                    else        MMA_BF16(acc[mt][nt], ah[mt], b[0], b[1]);
                }
        }
    }

    // ---- epilogue ----
#pragma unroll
    for (int mt = 0; mt < 2; mt++) {
        const int m = bm + wm * 32 + mt * 16 + (lane >> 2);
#pragma unroll
        for (int nt = 0; nt < 8; nt++) {
            const int n = bn + wn * 64 + nt * 8 + ((lane & 3) << 1);
            float2 b2 = *(const float2*)(bias + n);
            float2 o0, o1;
            o0.x = acc[mt][nt][0] + b2.x;
            o0.y = acc[mt][nt][1] + b2.y;
            o1.x = acc[mt][nt][2] + b2.x;
            o1.y = acc[mt][nt][3] + b2.y;
            if (R) {
                float2 r0 = *(const float2*)(R + (size_t)m * N + n);
                float2 r1 = *(const float2*)(R + (size_t)(m + 8) * N + n);
                o0.x += r0.x; o0.y += r0.y;
                o1.x += r1.x; o1.y += r1.y;
            }
            *(float2*)(C + (size_t)m * N + n) = o0;
            *(float2*)(C + (size_t)(m + 8) * N + n) = o1;
        }
    }
}

// ================= RoPE: qkv fp32 -> split bf16 q,k in [B,H,L,HD] =================
__global__ void rope_apply_split_kernel() {
    int idx = blockIdx.x * blockDim.x + threadIdx.x;
    if (idx >= BB * LL * HH * 64) return;
    int d = idx & 63;
    int h = (idx >> 6) & (HH - 1);
    int bl = idx >> 10;
    int b = bl >> 11;
    int l = bl & (LL - 1);
    float c = g_cos[l * 64 + d];
    float s = g_sin[l * 64 + d];
    size_t src = (size_t)bl * D3 + h * HD + d;
    size_t dst = ((size_t)(b * HH + h) * LL + l) * HD + d;

    float q1 = g_qkv[src], q2 = g_qkv[src + 64];
    float qa = q1 * c - q2 * s;
    float qb = q2 * c + q1 * s;
    __nv_bfloat16 t;
    t = __float2bfloat16(qa); g_qh[dst] = t;      g_ql[dst] = __float2bfloat16(qa - __bfloat162float(t));
    t = __float2bfloat16(qb); g_qh[dst + 64] = t; g_ql[dst + 64] = __float2bfloat16(qb - __bfloat162float(t));

    size_t ks = src + DD;
    float k1 = g_qkv[ks], k2 = g_qkv[ks + 64];
    float ka = k1 * c - k2 * s;
    float kb = k2 * c + k1 * s;
    t = __float2bfloat16(ka); g_kh[dst] = t;      g_kl[dst] = __float2bfloat16(ka - __bfloat162float(t));
    t = __float2bfloat16(kb); g_kh[dst + 64] = t; g_kl[dst + 64] = __float2bfloat16(kb - __bfloat162float(t));
}

// ================= V transpose + split =================
__global__ void v_transpose_split_kernel() {
    __shared__ float t[32][33];
    int l0 = blockIdx.x * 32, d0 = blockIdx.y * 32, bh = blockIdx.z;
    int b = bh >> 4, h = bh & 15;
    int tx = threadIdx.x, ty = threadIdx.y;
#pragma unroll
    for (int r = 0; r < 4; r++) {
        int l = ty + r * 8;
        t[l][tx] = g_qkv[(size_t)(b * LL + l0 + l) * D3 + 2 * DD + h * HD + d0 + tx];
    }
    __syncthreads();
#pragma unroll
    for (int r = 0; r < 4; r++) {
        int d = ty + r * 8;
        float v = t[tx][d];
        __nv_bfloat16 hv = __float2bfloat16(v);
        size_t dst = ((size_t)bh * HD + d0 + d) * LL + l0 + tx;
        g_vth[dst] = hv;
        g_vtl[dst] = __float2bfloat16(v - __bfloat162float(hv));
    }
}

// ================= attention scores (bf16x3 MMA, 3-stage, 2 CTAs/SM) =================
#define ATT_STG 32768
#define ATT_SMEM (3 * ATT_STG)

__global__ void __launch_bounds__(256, 2) attn_scores_mma_kernel() {
    extern __shared__ char sm[];
    const int jb = blockIdx.x, ib = blockIdx.y, bh = blockIdx.z;
    if (jb > ib) return;
    const int tid = threadIdx.x, lane = tid & 31, wid = tid >> 5;
    const int wm = wid & 3, wn = wid >> 2;
    const uint32_t smb = smem_u32(sm);

    const __nv_bfloat16* Qh = g_qh + ((size_t)bh * LL + ib * 128) * HD;
    const __nv_bfloat16* Ql = g_ql + ((size_t)bh * LL + ib * 128) * HD;
    const __nv_bfloat16* Kh = g_kh + ((size_t)bh * LL + jb * 128) * HD;
    const __nv_bfloat16* Kl = g_kl + ((size_t)bh * LL + jb * 128) * HD;

    const int rowA_base = wm * 32 + (lane & 15);
    const int rowB_base = wn * 64 + (lane & 7) + ((lane >> 4) << 3);
    const uint32_t xorw = (uint32_t)((lane & 6) << 3);

    float acc[2][8][4];
#pragma unroll
    for (int i = 0; i < 2; i++)
#pragma unroll
        for (int j = 0; j < 8; j++)
#pragma unroll
            for (int q = 0; q < 4; q++) acc[i][j][q] = 0.f;

    auto issue = [&](int c, int stg) {
        const uint32_t sb = smb + (uint32_t)(stg * ATT_STG);
        const int k0 = c * 32;
#pragma unroll
        for (int i = 0; i < 8; i++) {
            int u = tid + (i << 8);
            int row = (u >> 2) & 127;
            int seg = u & 3;
            const __nv_bfloat16* src = (u < 512) ? Qh : (u < 1024) ? Ql : (u < 1536) ? Kh : Kl;
            uint32_t roff = (uint32_t)(u >> 9) * 8192;
            uint32_t dst = sb + roff + (uint32_t)(row * 64) +
                           (((uint32_t)(seg * 16)) ^ ((uint32_t)((row & 6) << 3)));
            CP_ASYNC16(dst, src + (size_t)row * HD + k0 + seg * 8);
        }
        CP_COMMIT();
    };

    issue(0, 0);
    issue(1, 1);
#pragma unroll 1
    for (int c = 0; c < 4; c++) {
        CP_WAIT1();
        __syncthreads();
        if (c + 2 < 4) issue(c + 2, (c + 2) % 3);
        else CP_COMMIT();
        const uint32_t stg = smb + (uint32_t)((c % 3) * ATT_STG);
#pragma unroll
        for (int kk = 0; kk < 2; kk++) {
            const uint32_t cbA = ((uint32_t)(kk * 32 + ((lane >> 4) << 4))) ^ xorw;
            const uint32_t cbB = ((uint32_t)(kk * 32 + (((lane >> 3) & 1) << 4))) ^ xorw;
            uint32_t ah[2][4], bh4[4][4], fb[4][4], fa[2][4];
#pragma unroll
            for (int mt = 0; mt < 2; mt++)
                LDSM4(ah[mt], stg + 0 + (uint32_t)((rowA_base + mt * 16) * 64) + cbA);
#pragma unroll
            for (int bt = 0; bt < 4; bt++)
                LDSM4(bh4[bt], stg + 16384 + (uint32_t)((rowB_base + bt * 16) * 64) + cbB);
#pragma unroll
            for (int mt = 0; mt < 2; mt++)
#pragma unroll
                for (int nt = 0; nt < 8; nt++) {
                    const uint32_t* b = bh4[nt >> 1];
                    if (nt & 1) MMA_BF16(acc[mt][nt], ah[mt], b[2], b[3]);
                    else        MMA_BF16(acc[mt][nt], ah[mt], b[0], b[1]);
                }
#pragma unroll
            for (int mt = 0; mt < 2; mt++)
                LDSM4(fa[mt], stg + 8192 + (uint32_t)((rowA_base + mt * 16) * 64) + cbA);
#pragma unroll
            for (int mt = 0; mt < 2; mt++)
#pragma unroll
                for (int nt = 0; nt < 8; nt++) {
                    const uint32_t* b = bh4[nt >> 1];
                    if (nt & 1) MMA_BF16(acc[mt][nt], fa[mt], b[2], b[3]);
                    else        MMA_BF16(acc[mt][nt], fa[mt], b[0], b[1]);
                }
#pragma unroll
            for (int bt = 0; bt < 4; bt++)
                LDSM4(fb[bt], stg + 24576 + (uint32_t)((rowB_base + bt * 16) * 64) + cbB);
#pragma unroll
            for (int mt = 0; mt < 2; mt++)
#pragma unroll
                for (int nt = 0; nt < 8; nt++) {
                    const uint32_t* b = fb[nt >> 1];
                    if (nt & 1) MMA_BF16(acc[mt][nt], ah[mt], b[2], b[3]);
                    else        MMA_BF16(acc[mt][nt], ah[mt], b[0], b[1]);
                }
        }
    }

    const float scale = 0.08838834764831845f;
#pragma unroll
    for (int mt = 0; mt < 2; mt++) {
        const int i0 = ib * 128 + wm * 32 + mt * 16 + (lane >> 2);
#pragma unroll
        for (int nt = 0; nt < 8; nt++) {
            const int j0 = jb * 128 + wn * 64 + nt * 8 + ((lane & 3) << 1);
            float2 o0, o1;
            o0.x = (j0     <= i0)     ? acc[mt][nt][0] * scale : -1e30f;
            o0.y = (j0 + 1 <= i0)     ? acc[mt][nt][1] * scale : -1e30f;
            o1.x = (j0     <= i0 + 8) ? acc[mt][nt][2] * scale : -1e30f;
            o1.y = (j0 + 1 <= i0 + 8) ? acc[mt][nt][3] * scale : -1e30f;
            *(float2*)(g_s + ((size_t)bh * LL + i0) * LL + j0) = o0;
            *(float2*)(g_s + ((size_t)bh * LL + i0 + 8) * LL + j0) = o1;
        }
    }
}

// ================= row softmax -> split bf16 P =================
__global__ void softmax_kernel() {
    int r = blockIdx.x;
    int i = r & (LL - 1);
    int len = ((i >> 6) + 1) << 6;
    int len2 = ((i >> 7) + 1) << 7;
    float* p = g_s + (size_t)r * LL;
    __nv_bfloat16* ph = g_ph + (size_t)r * LL;
    __nv_bfloat16* pl = g_pl + (size_t)r * LL;
    __shared__ float red[128];

    float m = -1e30f;
    for (int c = threadIdx.x; c < len; c += 128) m = fmaxf(m, p[c]);
    red[threadIdx.x] = m;
    __syncthreads();
    for (int s = 64; s > 0; s >>= 1) {
        if (threadIdx.x < s) red[threadIdx.x] = fmaxf(red[threadIdx.x], red[threadIdx.x + s]);
        __syncthreads();
    }
    m = red[0];
    __syncthreads();

    float sum = 0.f;
    for (int c = threadIdx.x; c < len; c += 128) {
        float e = expf(p[c] - m);
        p[c] = e;
        sum += e;
    }
    red[threadIdx.x] = sum;
    __syncthreads();
    for (int s = 64; s > 0; s >>= 1) {
        if (threadIdx.x < s) red[threadIdx.x] += red[threadIdx.x + s];
        __syncthreads();
    }
    float inv = 1.f / red[0];
    for (int c = threadIdx.x; c < len; c += 128) {
        float v = p[c] * inv;
        __nv_bfloat16 hv = __float2bfloat16(v);
        ph[c] = hv;
        pl[c] = __float2bfloat16(v - __bfloat162float(hv));
    }
    for (int c = len + threadIdx.x; c < len2; c += 128) {
        ph[c] = __float2bfloat16(0.f);
        pl[c] = __float2bfloat16(0.f);
    }
}

// ================= O = P @ V (bf16x3 MMA, 3-stage, 2 CTAs/SM) -> split o =================
__global__ void __launch_bounds__(256, 2) attn_pv_mma_kernel() {
    extern __shared__ char sm[];
    const int ib = blockIdx.x, bh = blockIdx.y;
    const int b = bh >> 4, h = bh & 15;
    const int tid = threadIdx.x, lane = tid & 31, wid = tid >> 5;
    const int wm = wid & 3, wn = wid >> 2;
    const uint32_t smb = smem_u32(sm);

    const __nv_bfloat16* Ph = g_ph + ((size_t)bh * LL + ib * 128) * LL;
    const __nv_bfloat16* Pl = g_pl + ((size_t)bh * LL + ib * 128) * LL;
    const __nv_bfloat16* Vh = g_vth + (size_t)bh * HD * LL;
    const __nv_bfloat16* Vl = g_vtl + (size_t)bh * HD * LL;

    const int rowA_base = wm * 32 + (lane & 15);
    const int rowB_base = wn * 64 + (lane & 7) + ((lane >> 4) << 3);
    const uint32_t xorw = (uint32_t)((lane & 6) << 3);

    float acc[2][8][4];
#pragma unroll
    for (int i = 0; i < 2; i++)
#pragma unroll
        for (int j = 0; j < 8; j++)
#pragma unroll
            for (int q = 0; q < 4; q++) acc[i][j][q] = 0.f;

    auto issue = [&](int c, int stg) {
        const uint32_t sb = smb + (uint32_t)(stg * ATT_STG);
        const int j0 = c * 32;
#pragma unroll
        for (int i = 0; i < 8; i++) {
            int u = tid + (i << 8);
            int row = (u >> 2) & 127;
            int seg = u & 3;
            const __nv_bfloat16* src = (u < 512) ? Ph : (u < 1024) ? Pl : (u < 1536) ? Vh : Vl;
            uint32_t roff = (uint32_t)(u >> 9) * 8192;
            uint32_t dst = sb + roff + (uint32_t)(row * 64) +
                           (((uint32_t)(seg * 16)) ^ ((uint32_t)((row & 6) << 3)));
            CP_ASYNC16(dst, src + (size_t)row * LL + j0 + seg * 8);
        }
        CP_COMMIT();
    };

    const int NC = (ib + 1) * 4;
    issue(0, 0);
    issue(1, 1);
#pragma unroll 1
    for (int c = 0; c < NC; c++) {
        CP_WAIT1();
        __syncthreads();
        if (c + 2 < NC) issue(c + 2, (c + 2) % 3);
        else CP_COMMIT();
        const uint32_t stg = smb + (uint32_t)((c % 3) * ATT_STG);
#pragma unroll
        for (int kk = 0; kk < 2; kk++) {
            const uint32_t cbA = ((uint32_t)(kk * 32 + ((lane >> 4) << 4))) ^ xorw;
            const uint32_t cbB = ((uint32_t)(kk * 32 + (((lane >> 3) & 1) << 4))) ^ xorw;
            uint32_t ah[2][4], bh4[4][4], fb[4][4], fa[2][4];
#pragma unroll
            for (int mt = 0; mt < 2; mt++)
                LDSM4(ah[mt], stg + 0 + (uint32_t)((rowA_base + mt * 16) * 64) + cbA);
#pragma unroll
            for (int bt = 0; bt < 4; bt++)
                LDSM4(bh4[bt], stg + 16384 + (uint32_t)((rowB_base + bt * 16) * 64) + cbB);
#pragma unroll
            for (int mt = 0; mt < 2; mt++)
#pragma unroll
                for (int nt = 0; nt < 8; nt++) {
                    const uint32_t* bb = bh4[nt >> 1];
                    if (nt & 1) MMA_BF16(acc[mt][nt], ah[mt], bb[2], bb[3]);
                    else        MMA_BF16(acc[mt][nt], ah[mt], bb[0], bb[1]);
                }
#pragma unroll
            for (int mt = 0; mt < 2; mt++)
                LDSM4(fa[mt], stg + 8192 + (uint32_t)((rowA_base + mt * 16) * 64) + cbA);
#pragma unroll
            for (int mt = 0; mt < 2; mt++)
#pragma unroll
                for (int nt = 0; nt < 8; nt++) {
                    const uint32_t* bb = bh4[nt >> 1];
                    if (nt & 1) MMA_BF16(acc[mt][nt], fa[mt], bb[2], bb[3]);
                    else        MMA_BF16(acc[mt][nt], fa[mt], bb[0], bb[1]);
                }
#pragma unroll
            for (int bt = 0; bt < 4; bt++)
                LDSM4(fb[bt], stg + 24576 + (uint32_t)((rowB_base + bt * 16) * 64) + cbB);
#pragma unroll
            for (int mt = 0; mt < 2; mt++)
#pragma unroll
                for (int nt = 0; nt < 8; nt++) {
                    const uint32_t* bb = fb[nt >> 1];
                    if (nt & 1) MMA_BF16(acc[mt][nt], ah[mt], bb[2], bb[3]);
                    else        MMA_BF16(acc[mt][nt], ah[mt], bb[0], bb[1]);
                }
        }
    }

#pragma unroll
    for (int mt = 0; mt < 2; mt++) {
        const int qi = ib * 128 + wm * 32 + mt * 16 + (lane >> 2);
#pragma unroll
        for (int nt = 0; nt < 8; nt++) {
            const int d = wn * 64 + nt * 8 + ((lane & 3) << 1);
            size_t base0 = (size_t)(b * LL + qi) * DD + h * HD + d;
            size_t base1 = (size_t)(b * LL + qi + 8) * DD + h * HD + d;
            float v0 = acc[mt][nt][0], v1 = acc[mt][nt][1];
            float v2 = acc[mt][nt][2], v3 = acc[mt][nt][3];
            __nv_bfloat16 h0 = __float2bfloat16(v0), h1 = __float2bfloat16(v1);
            __nv_bfloat16 h2 = __float2bfloat16(v2), h3 = __float2bfloat16(v3);
            *(__nv_bfloat162*)(g_ah + base0) = __halves2bfloat162(h0, h1);
            *(__nv_bfloat162*)(g_ah + base1) = __halves2bfloat162(h2, h3);
            *(__nv_bfloat162*)(g_al + base0) = __halves2bfloat162(
                __float2bfloat16(v0 - __bfloat162float(h0)),
                __float2bfloat16(v1 - __bfloat162float(h1)));
            *(__nv_bfloat162*)(g_al + base1) = __halves2bfloat162(
                __float2bfloat16(v2 - __bfloat162float(h2)),
                __float2bfloat16(v3 - __bfloat162float(h3)));
        }
    }
}

// ================= SwiGLU -> split bf16 =================
__global__ void swiglu_split_kernel() {
    size_t idx = (size_t)blockIdx.x * blockDim.x + threadIdx.x;
    if (idx >= (size_t)MROWS * D4) return;
    size_t row = idx >> 13;
    int col = (int)(idx & (D4 - 1));
    float gv = g_p[row * D8 + col];
    float vv = g_p[row * D8 + D4 + col];
    float r = gv / (1.f + expf(-gv)) * vv;
    __nv_bfloat16 hv = __float2bfloat16(r);
    g_ah[idx] = hv;
    g_al[idx] = __float2bfloat16(r - __bfloat162float(hv));
}

// ================= launch =================
extern "C" void kernel_launch(void* const* d_in, const int* in_sizes, int n_in,
                              void* d_out, int out_size) {
    const float* x    = (const float*)d_in[0];
    const float* Wqkv = (const float*)d_in[1];
    const float* bqkv = (const float*)d_in[2];
    const float* Wo   = (const float*)d_in[3];
    const float* bo   = (const float*)d_in[4];
    const float* g1   = (const float*)d_in[5];
    const float* g2   = (const float*)d_in[6];
    const float* Wp   = (const float*)d_in[7];
    const float* bp   = (const float*)d_in[8];
    const float* Wff  = (const float*)d_in[9];
    const float* bff  = (const float*)d_in[10];
    float* out = (float*)d_out;

    __nv_bfloat16 *ah, *al, *wqh, *wql, *woh, *wol, *wph, *wpl, *wfh, *wfl;
    float *qkv, *x1, *p;
    cudaGetSymbolAddress((void**)&ah,  g_ah);
    cudaGetSymbolAddress((void**)&al,  g_al);
    cudaGetSymbolAddress((void**)&wqh, g_WqkvT_hi);
    cudaGetSymbolAddress((void**)&wql, g_WqkvT_lo);
    cudaGetSymbolAddress((void**)&woh, g_WoT_hi);
    cudaGetSymbolAddress((void**)&wol, g_WoT_lo);
    cudaGetSymbolAddress((void**)&wph, g_WpT_hi);
    cudaGetSymbolAddress((void**)&wpl, g_WpT_lo);
    cudaGetSymbolAddress((void**)&wfh, g_WffT_hi);
    cudaGetSymbolAddress((void**)&wfl, g_WffT_lo);
    cudaGetSymbolAddress((void**)&qkv, g_qkv);
    cudaGetSymbolAddress((void**)&x1,  g_x1);
    cudaGetSymbolAddress((void**)&p,   g_p);

    cudaFuncSetAttribute(gemm_mma3_kernel,
                         cudaFuncAttributeMaxDynamicSharedMemorySize, GEMM_SMEM);
    cudaFuncSetAttribute(attn_scores_mma_kernel,
                         cudaFuncAttributeMaxDynamicSharedMemorySize, ATT_SMEM);
    cudaFuncSetAttribute(attn_pv_mma_kernel,
                         cudaFuncAttributeMaxDynamicSharedMemorySize, ATT_SMEM);

    dim3 tb(32, 8);

    // 1) h = rms(x, g1), split
    rmsnorm_split_kernel<<<MROWS, 256>>>(x, g1, ah, al);
    // 2) Wqkv transpose/split
    transpose_split_kernel<<<dim3(D3 / 32, DD / 32), tb>>>(Wqkv, wqh, wql, DD, D3);
    // 3) RoPE tables
    rope_table_kernel<<<LL, 64>>>();
    // 4) qkv = h @ Wqkv + bqkv   (launch #4 — profiled)
    gemm_mma3_kernel<<<dim3(MROWS / TM, D3 / TN), 256, GEMM_SMEM>>>(
        ah, al, wqh, wql, bqkv, nullptr, qkv, MROWS, D3, DD);
    // 5) RoPE apply + split q,k
    {
        int total = BB * LL * HH * 64;
        rope_apply_split_kernel<<<(total + 255) / 256, 256>>>();
    }
    // 6) V transpose + split
    v_transpose_split_kernel<<<dim3(LL / 32, HD / 32, BB * HH), tb>>>();
    // 7) scores
    attn_scores_mma_kernel<<<dim3(LL / 128, LL / 128, BB * HH), 256, ATT_SMEM>>>();
    // 8) softmax -> split P
    softmax_kernel<<<BB * HH * LL, 128>>>();
    // 9) O = P @ V
    attn_pv_mma_kernel<<<dim3(LL / 128, BB * HH), 256, ATT_SMEM>>>();
    // 10) Wo transpose/split
    transpose_split_kernel<<<dim3(DD / 32, DD / 32), tb>>>(Wo, woh, wol, DD, DD);
    // 11) x1 = o @ Wo + bo + x
    gemm_mma3_kernel<<<dim3(MROWS / TM, DD / TN), 256, GEMM_SMEM>>>(
        ah, al, woh, wol, bo, x, x1, MROWS, DD, DD);
    // 12) h2 = rms(x1, g2), split
    rmsnorm_split_kernel<<<MROWS, 256>>>(x1, g2, ah, al);
    // 13) Wp transpose/split
    transpose_split_kernel<<<dim3(D8 / 32, DD / 32), tb>>>(Wp, wph, wpl, DD, D8);
    // 14) p = h2 @ Wp + bp
    gemm_mma3_kernel<<<dim3(MROWS / TM, D8 / TN), 256, GEMM_SMEM>>>(
        ah, al, wph, wpl, bp, nullptr, p, MROWS, D8, DD);
    // 15) ffh = silu(gate) * value, split
    {
        size_t total = (size_t)MROWS * D4;
        swiglu_split_kernel<<<(unsigned)((total + 255) / 256), 256>>>();
    }
    // 16) Wff transpose/split
    transpose_split_kernel<<<dim3(DD / 32, D4 / 32), tb>>>(Wff, wfh, wfl, D4, DD);
    // 17) out = ffh @ Wff + bff + x1
    gemm_mma3_kernel<<<dim3(MROWS / TM, DD / TN), 256, GEMM_SMEM>>>(
        ah, al, wfh, wfl, bff, x1, out, MROWS, DD, D4);
}

// round 8
// speedup vs baseline: 1.1524x; 1.0202x over previous
#include <cuda_runtime.h>
#include <cuda_bf16.h>
#include <math.h>
#include <stdint.h>

// Problem constants
#define BB 2
#define LL 2048
#define DD 2048
#define HH 16
#define HD 128
#define MROWS (BB * LL)        // 4096
#define D3 (3 * DD)            // 6144
#define D8 (8 * DD)            // 16384
#define D4 (4 * DD)            // 8192

// ---------------- scratch ----------------
__device__ float g_qkv[(size_t)MROWS * D3];
__device__ float g_s  [(size_t)BB * HH * LL * LL];
__device__ float g_x1 [(size_t)MROWS * DD];
__device__ float g_p  [(size_t)MROWS * D8];
__device__ float g_cos[LL * 64];
__device__ float g_sin[LL * 64];

__device__ __align__(16) __nv_bfloat16 g_ah[(size_t)MROWS * D4];
__device__ __align__(16) __nv_bfloat16 g_al[(size_t)MROWS * D4];

__device__ __align__(16) __nv_bfloat16 g_qh[(size_t)BB * HH * LL * HD];
__device__ __align__(16) __nv_bfloat16 g_ql[(size_t)BB * HH * LL * HD];
__device__ __align__(16) __nv_bfloat16 g_kh[(size_t)BB * HH * LL * HD];
__device__ __align__(16) __nv_bfloat16 g_kl[(size_t)BB * HH * LL * HD];
__device__ __align__(16) __nv_bfloat16 g_vth[(size_t)BB * HH * HD * LL];
__device__ __align__(16) __nv_bfloat16 g_vtl[(size_t)BB * HH * HD * LL];
__device__ __align__(16) __nv_bfloat16 g_ph[(size_t)BB * HH * LL * LL];
__device__ __align__(16) __nv_bfloat16 g_pl[(size_t)BB * HH * LL * LL];

__device__ __align__(16) __nv_bfloat16 g_WqkvT_hi[(size_t)D3 * DD];
__device__ __align__(16) __nv_bfloat16 g_WqkvT_lo[(size_t)D3 * DD];
__device__ __align__(16) __nv_bfloat16 g_WoT_hi[(size_t)DD * DD];
__device__ __align__(16) __nv_bfloat16 g_WoT_lo[(size_t)DD * DD];
__device__ __align__(16) __nv_bfloat16 g_WpT_hi[(size_t)D8 * DD];
__device__ __align__(16) __nv_bfloat16 g_WpT_lo[(size_t)D8 * DD];
__device__ __align__(16) __nv_bfloat16 g_WffT_hi[(size_t)DD * D4];
__device__ __align__(16) __nv_bfloat16 g_WffT_lo[(size_t)DD * D4];

// ================= helpers =================
__device__ __forceinline__ uint32_t smem_u32(const void* p) {
    uint32_t a;
    asm("{ .reg .u64 t; cvta.to.shared.u64 t, %1; cvt.u32.u64 %0, t; }" : "=r"(a) : "l"(p));
    return a;
}

#define CP_ASYNC16(dst, src) \
    asm volatile("cp.async.cg.shared.global [%0], [%1], 16;" :: "r"(dst), "l"(src) : "memory")
#define CP_COMMIT() asm volatile("cp.async.commit_group;" ::: "memory")
#define CP_WAIT1()  asm volatile("cp.async.wait_group 1;" ::: "memory")

#define LDSM4(r, addr) \
    asm volatile("ldmatrix.sync.aligned.m8n8.x4.shared.b16 {%0,%1,%2,%3}, [%4];" \
        : "=r"((r)[0]), "=r"((r)[1]), "=r"((r)[2]), "=r"((r)[3]) : "r"(addr))

#define MMA_BF16(d, a, b0, b1) \
    asm volatile("mma.sync.aligned.m16n8k16.row.col.f32.bf16.bf16.f32 " \
        "{%0,%1,%2,%3}, {%4,%5,%6,%7}, {%8,%9}, {%0,%1,%2,%3};" \
        : "+f"((d)[0]), "+f"((d)[1]), "+f"((d)[2]), "+f"((d)[3]) \
        : "r"((a)[0]), "r"((a)[1]), "r"((a)[2]), "r"((a)[3]), "r"(b0), "r"(b1))

// ================= RoPE tables =================
__global__ void rope_table_kernel() {
    int p = blockIdx.x, i = threadIdx.x;
    double inv_freq = pow(10000.0, -(double)(2 * i) / (double)HD);
    double ang = (double)p * inv_freq;
    g_cos[p * 64 + i] = (float)cos(ang);
    g_sin[p * 64 + i] = (float)sin(ang);
}

// ================= RMSNorm -> split bf16 hi/lo =================
__global__ void rmsnorm_split_kernel(const float* __restrict__ x,
                                     const float* __restrict__ g,
                                     __nv_bfloat16* __restrict__ hi,
                                     __nv_bfloat16* __restrict__ lo) {
    int row = blockIdx.x;
    const float* xr = x + (size_t)row * DD;
    float ss = 0.f;
    for (int c = threadIdx.x * 4; c < DD; c += blockDim.x * 4) {
        float4 v = *(const float4*)(xr + c);
        ss += v.x * v.x + v.y * v.y + v.z * v.z + v.w * v.w;
    }
    __shared__ float red[256];
    red[threadIdx.x] = ss;
    __syncthreads();
    for (int s = blockDim.x / 2; s > 0; s >>= 1) {
        if (threadIdx.x < s) red[threadIdx.x] += red[threadIdx.x + s];
        __syncthreads();
    }
    float scale = rsqrtf(red[0] / (float)DD + 1e-8f);
    for (int c = threadIdx.x * 4; c < DD; c += blockDim.x * 4) {
        float4 v = *(const float4*)(xr + c);
        float4 gv = *(const float4*)(g + c);
        float y[4] = {v.x * scale * gv.x, v.y * scale * gv.y,
                      v.z * scale * gv.z, v.w * scale * gv.w};
#pragma unroll
        for (int j = 0; j < 4; j++) {
            __nv_bfloat16 h = __float2bfloat16(y[j]);
            hi[(size_t)row * DD + c + j] = h;
            lo[(size_t)row * DD + c + j] = __float2bfloat16(y[j] - __bfloat162float(h));
        }
    }
}

// ================= weight transpose + split =================
__global__ void transpose_split_kernel(const float* __restrict__ W,
                                       __nv_bfloat16* __restrict__ Thi,
                                       __nv_bfloat16* __restrict__ Tlo,
                                       int K, int N) {
    __shared__ float t[32][33];
    int n0 = blockIdx.x * 32, k0 = blockIdx.y * 32;
    int tx = threadIdx.x, ty = threadIdx.y;
#pragma unroll
    for (int r = 0; r < 4; r++) {
        int k = ty + r * 8;
        t[k][tx] = W[(size_t)(k0 + k) * N + n0 + tx];
    }
    __syncthreads();
#pragma unroll
    for (int r = 0; r < 4; r++) {
        int n = ty + r * 8;
        float v = t[tx][n];
        __nv_bfloat16 h = __float2bfloat16(v);
        Thi[(size_t)(n0 + n) * K + k0 + tx] = h;
        Tlo[(size_t)(n0 + n) * K + k0 + tx] = __float2bfloat16(v - __bfloat162float(h));
    }
}

// ====== mma.sync bf16x3 GEMM: 128x128 tile, 256 threads, 3-stage, 2 CTAs/SM ======
#define TM 128
#define TN 128
#define KC 32
#define AHI_OFF 0
#define ALO_OFF 8192
#define BHI_OFF 16384
#define BLO_OFF 24576
#define STG_BYTES 32768
#define GEMM_SMEM (3 * STG_BYTES)

__global__ void __launch_bounds__(256, 2) gemm_mma3_kernel(
    const __nv_bfloat16* __restrict__ Ahi, const __nv_bfloat16* __restrict__ Alo,
    const __nv_bfloat16* __restrict__ Bhi, const __nv_bfloat16* __restrict__ Blo,
    const float* __restrict__ bias, const float* __restrict__ R,
    float* __restrict__ C, int M, int N, int K)
{
    extern __shared__ char sm[];
    const int tid = threadIdx.x;
    const int lane = tid & 31;
    const int wid = tid >> 5;
    const int wm = wid & 3;
    const int wn = wid >> 2;
    const int bm = blockIdx.x * TM;
    const int bn = blockIdx.y * TN;
    const uint32_t smb = smem_u32(sm);

    const int rowA_base = wm * 32 + (lane & 15);
    const int rowB_base = wn * 64 + (lane & 7) + ((lane >> 4) << 3);
    const uint32_t xorw = (uint32_t)((lane & 6) << 3);

    float acc[2][8][4];
#pragma unroll
    for (int i = 0; i < 2; i++)
#pragma unroll
        for (int j = 0; j < 8; j++)
#pragma unroll
            for (int q = 0; q < 4; q++) acc[i][j][q] = 0.f;

    auto issue_chunk = [&](int k0, int stg) {
        const uint32_t sbase = smb + stg * STG_BYTES;
#pragma unroll
        for (int i = 0; i < 8; i++) {
            int u = tid + (i << 8);
            const __nv_bfloat16* src;
            uint32_t roff;
            int row;
            if (u < 512)       { row = u >> 2;          src = Ahi + (size_t)(bm + row) * K; roff = AHI_OFF; }
            else if (u < 1024) { row = (u - 512) >> 2;  src = Alo + (size_t)(bm + row) * K; roff = ALO_OFF; }
            else if (u < 1536) { row = (u - 1024) >> 2; src = Bhi + (size_t)(bn + row) * K; roff = BHI_OFF; }
            else               { row = (u - 1536) >> 2; src = Blo + (size_t)(bn + row) * K; roff = BLO_OFF; }
            int seg = u & 3;
            uint32_t dst = sbase + roff + (uint32_t)(row * 64) +
                           (((uint32_t)(seg * 16)) ^ ((uint32_t)((row & 6) << 3)));
            CP_ASYNC16(dst, src + k0 + seg * 8);
        }
        CP_COMMIT();
    };

    const int NC = K / KC;
    issue_chunk(0, 0);
    issue_chunk(KC, 1);

    for (int c = 0; c < NC; ++c) {
        CP_WAIT1();
        __syncthreads();
        if (c + 2 < NC) issue_chunk((c + 2) * KC, (c + 2) % 3);
        else CP_COMMIT();

        const uint32_t stg = smb + (uint32_t)((c % 3) * STG_BYTES);

#pragma unroll
        for (int kk = 0; kk < 2; kk++) {
            const uint32_t cbA = ((uint32_t)(kk * 32 + ((lane >> 4) << 4))) ^ xorw;
            const uint32_t cbB = ((uint32_t)(kk * 32 + (((lane >> 3) & 1) << 4))) ^ xorw;

            uint32_t ah[2][4], bh4[4][4], fa[2][4], fb[4][4];
            // front-load ah, bh AND fb (B-lo) so fb's latency hides under hh MMAs
#pragma unroll
            for (int mt = 0; mt < 2; mt++)
                LDSM4(ah[mt], stg + AHI_OFF + (uint32_t)((rowA_base + mt * 16) * 64) + cbA);
#pragma unroll
            for (int bt = 0; bt < 4; bt++)
                LDSM4(bh4[bt], stg + BHI_OFF + (uint32_t)((rowB_base + bt * 16) * 64) + cbB);
#pragma unroll
            for (int bt = 0; bt < 4; bt++)
                LDSM4(fb[bt], stg + BLO_OFF + (uint32_t)((rowB_base + bt * 16) * 64) + cbB);
            // hi x hi
#pragma unroll
            for (int mt = 0; mt < 2; mt++)
#pragma unroll
                for (int nt = 0; nt < 8; nt++) {
                    const uint32_t* b = bh4[nt >> 1];
                    if (nt & 1) MMA_BF16(acc[mt][nt], ah[mt], b[2], b[3]);
                    else        MMA_BF16(acc[mt][nt], ah[mt], b[0], b[1]);
                }
            // hi x lo (fb already in flight / ready)
#pragma unroll
            for (int mt = 0; mt < 2; mt++)
#pragma unroll
                for (int nt = 0; nt < 8; nt++) {
                    const uint32_t* b = fb[nt >> 1];
                    if (nt & 1) MMA_BF16(acc[mt][nt], ah[mt], b[2], b[3]);
                    else        MMA_BF16(acc[mt][nt], ah[mt], b[0], b[1]);
                }
            // lo x hi
#pragma unroll
            for (int mt = 0; mt < 2; mt++)
                LDSM4(fa[mt], stg + ALO_OFF + (uint32_t)((rowA_base + mt * 16) * 64) + cbA);
#pragma unroll
            for (int mt = 0; mt < 2; mt++)
#pragma unroll
                for (int nt = 0; nt < 8; nt++) {
                    const uint32_t* b = bh4[nt >> 1];
                    if (nt & 1) MMA_BF16(acc[mt][nt], fa[mt], b[2], b[3]);
                    else        MMA_BF16(acc[mt][nt], fa[mt], b[0], b[1]);
                }
        }
    }

    // ---- epilogue ----
#pragma unroll
    for (int mt = 0; mt < 2; mt++) {
        const int m = bm + wm * 32 + mt * 16 + (lane >> 2);
#pragma unroll
        for (int nt = 0; nt < 8; nt++) {
            const int n = bn + wn * 64 + nt * 8 + ((lane & 3) << 1);
            float2 b2 = *(const float2*)(bias + n);
            float2 o0, o1;
            o0.x = acc[mt][nt][0] + b2.x;
            o0.y = acc[mt][nt][1] + b2.y;
            o1.x = acc[mt][nt][2] + b2.x;
            o1.y = acc[mt][nt][3] + b2.y;
            if (R) {
                float2 r0 = *(const float2*)(R + (size_t)m * N + n);
                float2 r1 = *(const float2*)(R + (size_t)(m + 8) * N + n);
                o0.x += r0.x; o0.y += r0.y;
                o1.x += r1.x; o1.y += r1.y;
            }
            *(float2*)(C + (size_t)m * N + n) = o0;
            *(float2*)(C + (size_t)(m + 8) * N + n) = o1;
        }
    }
}

// ================= RoPE: qkv fp32 -> split bf16 q,k in [B,H,L,HD] =================
__global__ void rope_apply_split_kernel() {
    int idx = blockIdx.x * blockDim.x + threadIdx.x;
    if (idx >= BB * LL * HH * 64) return;
    int d = idx & 63;
    int h = (idx >> 6) & (HH - 1);
    int bl = idx >> 10;
    int b = bl >> 11;
    int l = bl & (LL - 1);
    float c = g_cos[l * 64 + d];
    float s = g_sin[l * 64 + d];
    size_t src = (size_t)bl * D3 + h * HD + d;
    size_t dst = ((size_t)(b * HH + h) * LL + l) * HD + d;

    float q1 = g_qkv[src], q2 = g_qkv[src + 64];
    float qa = q1 * c - q2 * s;
    float qb = q2 * c + q1 * s;
    __nv_bfloat16 t;
    t = __float2bfloat16(qa); g_qh[dst] = t;      g_ql[dst] = __float2bfloat16(qa - __bfloat162float(t));
    t = __float2bfloat16(qb); g_qh[dst + 64] = t; g_ql[dst + 64] = __float2bfloat16(qb - __bfloat162float(t));

    size_t ks = src + DD;
    float k1 = g_qkv[ks], k2 = g_qkv[ks + 64];
    float ka = k1 * c - k2 * s;
    float kb = k2 * c + k1 * s;
    t = __float2bfloat16(ka); g_kh[dst] = t;      g_kl[dst] = __float2bfloat16(ka - __bfloat162float(t));
    t = __float2bfloat16(kb); g_kh[dst + 64] = t; g_kl[dst + 64] = __float2bfloat16(kb - __bfloat162float(t));
}

// ================= V transpose + split =================
__global__ void v_transpose_split_kernel() {
    __shared__ float t[32][33];
    int l0 = blockIdx.x * 32, d0 = blockIdx.y * 32, bh = blockIdx.z;
    int b = bh >> 4, h = bh & 15;
    int tx = threadIdx.x, ty = threadIdx.y;
#pragma unroll
    for (int r = 0; r < 4; r++) {
        int l = ty + r * 8;
        t[l][tx] = g_qkv[(size_t)(b * LL + l0 + l) * D3 + 2 * DD + h * HD + d0 + tx];
    }
    __syncthreads();
#pragma unroll
    for (int r = 0; r < 4; r++) {
        int d = ty + r * 8;
        float v = t[tx][d];
        __nv_bfloat16 hv = __float2bfloat16(v);
        size_t dst = ((size_t)bh * HD + d0 + d) * LL + l0 + tx;
        g_vth[dst] = hv;
        g_vtl[dst] = __float2bfloat16(v - __bfloat162float(hv));
    }
}

// ================= attention scores (bf16x3 MMA, 3-stage, 2 CTAs/SM) =================
#define ATT_STG 32768
#define ATT_SMEM (3 * ATT_STG)

__global__ void __launch_bounds__(256, 2) attn_scores_mma_kernel() {
    extern __shared__ char sm[];
    const int jb = blockIdx.x, ib = blockIdx.y, bh = blockIdx.z;
    if (jb > ib) return;
    const int tid = threadIdx.x, lane = tid & 31, wid = tid >> 5;
    const int wm = wid & 3, wn = wid >> 2;
    const uint32_t smb = smem_u32(sm);

    const __nv_bfloat16* Qh = g_qh + ((size_t)bh * LL + ib * 128) * HD;
    const __nv_bfloat16* Ql = g_ql + ((size_t)bh * LL + ib * 128) * HD;
    const __nv_bfloat16* Kh = g_kh + ((size_t)bh * LL + jb * 128) * HD;
    const __nv_bfloat16* Kl = g_kl + ((size_t)bh * LL + jb * 128) * HD;

    const int rowA_base = wm * 32 + (lane & 15);
    const int rowB_base = wn * 64 + (lane & 7) + ((lane >> 4) << 3);
    const uint32_t xorw = (uint32_t)((lane & 6) << 3);

    float acc[2][8][4];
#pragma unroll
    for (int i = 0; i < 2; i++)
#pragma unroll
        for (int j = 0; j < 8; j++)
#pragma unroll
            for (int q = 0; q < 4; q++) acc[i][j][q] = 0.f;

    auto issue = [&](int c, int stg) {
        const uint32_t sb = smb + (uint32_t)(stg * ATT_STG);
        const int k0 = c * 32;
#pragma unroll
        for (int i = 0; i < 8; i++) {
            int u = tid + (i << 8);
            int row = (u >> 2) & 127;
            int seg = u & 3;
            const __nv_bfloat16* src = (u < 512) ? Qh : (u < 1024) ? Ql : (u < 1536) ? Kh : Kl;
            uint32_t roff = (uint32_t)(u >> 9) * 8192;
            uint32_t dst = sb + roff + (uint32_t)(row * 64) +
                           (((uint32_t)(seg * 16)) ^ ((uint32_t)((row & 6) << 3)));
            CP_ASYNC16(dst, src + (size_t)row * HD + k0 + seg * 8);
        }
        CP_COMMIT();
    };

    issue(0, 0);
    issue(1, 1);
#pragma unroll 1
    for (int c = 0; c < 4; c++) {
        CP_WAIT1();
        __syncthreads();
        if (c + 2 < 4) issue(c + 2, (c + 2) % 3);
        else CP_COMMIT();
        const uint32_t stg = smb + (uint32_t)((c % 3) * ATT_STG);
#pragma unroll
        for (int kk = 0; kk < 2; kk++) {
            const uint32_t cbA = ((uint32_t)(kk * 32 + ((lane >> 4) << 4))) ^ xorw;
            const uint32_t cbB = ((uint32_t)(kk * 32 + (((lane >> 3) & 1) << 4))) ^ xorw;
            uint32_t ah[2][4], bh4[4][4], fb[4][4], fa[2][4];
#pragma unroll
            for (int mt = 0; mt < 2; mt++)
                LDSM4(ah[mt], stg + 0 + (uint32_t)((rowA_base + mt * 16) * 64) + cbA);
#pragma unroll
            for (int bt = 0; bt < 4; bt++)
                LDSM4(bh4[bt], stg + 16384 + (uint32_t)((rowB_base + bt * 16) * 64) + cbB);
#pragma unroll
            for (int bt = 0; bt < 4; bt++)
                LDSM4(fb[bt], stg + 24576 + (uint32_t)((rowB_base + bt * 16) * 64) + cbB);
#pragma unroll
            for (int mt = 0; mt < 2; mt++)
#pragma unroll
                for (int nt = 0; nt < 8; nt++) {
                    const uint32_t* b = bh4[nt >> 1];
                    if (nt & 1) MMA_BF16(acc[mt][nt], ah[mt], b[2], b[3]);
                    else        MMA_BF16(acc[mt][nt], ah[mt], b[0], b[1]);
                }
#pragma unroll
            for (int mt = 0; mt < 2; mt++)
#pragma unroll
                for (int nt = 0; nt < 8; nt++) {
                    const uint32_t* b = fb[nt >> 1];
                    if (nt & 1) MMA_BF16(acc[mt][nt], ah[mt], b[2], b[3]);
                    else        MMA_BF16(acc[mt][nt], ah[mt], b[0], b[1]);
                }
#pragma unroll
            for (int mt = 0; mt < 2; mt++)
                LDSM4(fa[mt], stg + 8192 + (uint32_t)((rowA_base + mt * 16) * 64) + cbA);
#pragma unroll
            for (int mt = 0; mt < 2; mt++)
#pragma unroll
                for (int nt = 0; nt < 8; nt++) {
                    const uint32_t* b = bh4[nt >> 1];
                    if (nt & 1) MMA_BF16(acc[mt][nt], fa[mt], b[2], b[3]);
                    else        MMA_BF16(acc[mt][nt], fa[mt], b[0], b[1]);
                }
        }
    }

    const float scale = 0.08838834764831845f;
#pragma unroll
    for (int mt = 0; mt < 2; mt++) {
        const int i0 = ib * 128 + wm * 32 + mt * 16 + (lane >> 2);
#pragma unroll
        for (int nt = 0; nt < 8; nt++) {
            const int j0 = jb * 128 + wn * 64 + nt * 8 + ((lane & 3) << 1);
            float2 o0, o1;
            o0.x = (j0     <= i0)     ? acc[mt][nt][0] * scale : -1e30f;
            o0.y = (j0 + 1 <= i0)     ? acc[mt][nt][1] * scale : -1e30f;
            o1.x = (j0     <= i0 + 8) ? acc[mt][nt][2] * scale : -1e30f;
            o1.y = (j0 + 1 <= i0 + 8) ? acc[mt][nt][3] * scale : -1e30f;
            *(float2*)(g_s + ((size_t)bh * LL + i0) * LL + j0) = o0;
            *(float2*)(g_s + ((size_t)bh * LL + i0 + 8) * LL + j0) = o1;
        }
    }
}

// ================= row softmax -> split bf16 P (vectorized) =================
__global__ void softmax_kernel() {
    int r = blockIdx.x;
    int i = r & (LL - 1);
    int len = ((i >> 6) + 1) << 6;       // multiple of 64
    int len2 = ((i >> 7) + 1) << 7;      // multiple of 128
    float* p = g_s + (size_t)r * LL;
    __nv_bfloat16* ph = g_ph + (size_t)r * LL;
    __nv_bfloat16* pl = g_pl + (size_t)r * LL;
    __shared__ float red[128];

    float m = -1e30f;
    for (int c = threadIdx.x * 4; c < len; c += 512) {
        float4 v = *(const float4*)(p + c);
        m = fmaxf(m, fmaxf(fmaxf(v.x, v.y), fmaxf(v.z, v.w)));
    }
    // handle tail when len not multiple of 512: the loop above covers c<len only
    red[threadIdx.x] = m;
    __syncthreads();
    for (int s = 64; s > 0; s >>= 1) {
        if (threadIdx.x < s) red[threadIdx.x] = fmaxf(red[threadIdx.x], red[threadIdx.x + s]);
        __syncthreads();
    }
    m = red[0];
    __syncthreads();

    float sum = 0.f;
    for (int c = threadIdx.x * 4; c < len; c += 512) {
        float4 v = *(const float4*)(p + c);
        v.x = expf(v.x - m); v.y = expf(v.y - m);
        v.z = expf(v.z - m); v.w = expf(v.w - m);
        *(float4*)(p + c) = v;
        sum += v.x + v.y + v.z + v.w;
    }
    red[threadIdx.x] = sum;
    __syncthreads();
    for (int s = 64; s > 0; s >>= 1) {
        if (threadIdx.x < s) red[threadIdx.x] += red[threadIdx.x + s];
        __syncthreads();
    }
    float inv = 1.f / red[0];
    for (int c = threadIdx.x * 4; c < len; c += 512) {
        float4 v = *(const float4*)(p + c);
        float y[4] = {v.x * inv, v.y * inv, v.z * inv, v.w * inv};
        __nv_bfloat16 h0 = __float2bfloat16(y[0]), h1 = __float2bfloat16(y[1]);
        __nv_bfloat16 h2 = __float2bfloat16(y[2]), h3 = __float2bfloat16(y[3]);
        __nv_bfloat162 hv0 = __halves2bfloat162(h0, h1);
        __nv_bfloat162 hv1 = __halves2bfloat162(h2, h3);
        *(__nv_bfloat162*)(ph + c) = hv0;
        *(__nv_bfloat162*)(ph + c + 2) = hv1;
        *(__nv_bfloat162*)(pl + c) = __halves2bfloat162(
            __float2bfloat16(y[0] - __bfloat162float(h0)),
            __float2bfloat16(y[1] - __bfloat162float(h1)));
        *(__nv_bfloat162*)(pl + c + 2) = __halves2bfloat162(
            __float2bfloat16(y[2] - __bfloat162float(h2)),
            __float2bfloat16(y[3] - __bfloat162float(h3)));
    }
    for (int c = len + threadIdx.x * 4; c < len2; c += 512) {
        *(__nv_bfloat162*)(ph + c) = __halves2bfloat162(__float2bfloat16(0.f), __float2bfloat16(0.f));
        *(__nv_bfloat162*)(ph + c + 2) = __halves2bfloat162(__float2bfloat16(0.f), __float2bfloat16(0.f));
        *(__nv_bfloat162*)(pl + c) = __halves2bfloat162(__float2bfloat16(0.f), __float2bfloat16(0.f));
        *(__nv_bfloat162*)(pl + c + 2) = __halves2bfloat162(__float2bfloat16(0.f), __float2bfloat16(0.f));
    }
}

// ================= O = P @ V (bf16x3 MMA, 3-stage, 2 CTAs/SM) -> split o =================
__global__ void __launch_bounds__(256, 2) attn_pv_mma_kernel() {
    extern __shared__ char sm[];
    const int ib = blockIdx.x, bh = blockIdx.y;
    const int b = bh >> 4, h = bh & 15;
    const int tid = threadIdx.x, lane = tid & 31, wid = tid >> 5;
    const int wm = wid & 3, wn = wid >> 2;
    const uint32_t smb = smem_u32(sm);

    const __nv_bfloat16* Ph = g_ph + ((size_t)bh * LL + ib * 128) * LL;
    const __nv_bfloat16* Pl = g_pl + ((size_t)bh * LL + ib * 128) * LL;
    const __nv_bfloat16* Vh = g_vth + (size_t)bh * HD * LL;
    const __nv_bfloat16* Vl = g_vtl + (size_t)bh * HD * LL;

    const int rowA_base = wm * 32 + (lane & 15);
    const int rowB_base = wn * 64 + (lane & 7) + ((lane >> 4) << 3);
    const uint32_t xorw = (uint32_t)((lane & 6) << 3);

    float acc[2][8][4];
#pragma unroll
    for (int i = 0; i < 2; i++)
#pragma unroll
        for (int j = 0; j < 8; j++)
#pragma unroll
            for (int q = 0; q < 4; q++) acc[i][j][q] = 0.f;

    auto issue = [&](int c, int stg) {
        const uint32_t sb = smb + (uint32_t)(stg * ATT_STG);
        const int j0 = c * 32;
#pragma unroll
        for (int i = 0; i < 8; i++) {
            int u = tid + (i << 8);
            int row = (u >> 2) & 127;
            int seg = u & 3;
            const __nv_bfloat16* src = (u < 512) ? Ph : (u < 1024) ? Pl : (u < 1536) ? Vh : Vl;
            uint32_t roff = (uint32_t)(u >> 9) * 8192;
            uint32_t dst = sb + roff + (uint32_t)(row * 64) +
                           (((uint32_t)(seg * 16)) ^ ((uint32_t)((row & 6) << 3)));
            CP_ASYNC16(dst, src + (size_t)row * LL + j0 + seg * 8);
        }
        CP_COMMIT();
    };

    const int NC = (ib + 1) * 4;
    issue(0, 0);
    issue(1, 1);
#pragma unroll 1
    for (int c = 0; c < NC; c++) {
        CP_WAIT1();
        __syncthreads();
        if (c + 2 < NC) issue(c + 2, (c + 2) % 3);
        else CP_COMMIT();
        const uint32_t stg = smb + (uint32_t)((c % 3) * ATT_STG);
#pragma unroll
        for (int kk = 0; kk < 2; kk++) {
            const uint32_t cbA = ((uint32_t)(kk * 32 + ((lane >> 4) << 4))) ^ xorw;
            const uint32_t cbB = ((uint32_t)(kk * 32 + (((lane >> 3) & 1) << 4))) ^ xorw;
            uint32_t ah[2][4], bh4[4][4], fb[4][4], fa[2][4];
#pragma unroll
            for (int mt = 0; mt < 2; mt++)
                LDSM4(ah[mt], stg + 0 + (uint32_t)((rowA_base + mt * 16) * 64) + cbA);
#pragma unroll
            for (int bt = 0; bt < 4; bt++)
                LDSM4(bh4[bt], stg + 16384 + (uint32_t)((rowB_base + bt * 16) * 64) + cbB);
#pragma unroll
            for (int bt = 0; bt < 4; bt++)
                LDSM4(fb[bt], stg + 24576 + (uint32_t)((rowB_base + bt * 16) * 64) + cbB);
#pragma unroll
            for (int mt = 0; mt < 2; mt++)
#pragma unroll
                for (int nt = 0; nt < 8; nt++) {
                    const uint32_t* bb = bh4[nt >> 1];
                    if (nt & 1) MMA_BF16(acc[mt][nt], ah[mt], bb[2], bb[3]);
                    else        MMA_BF16(acc[mt][nt], ah[mt], bb[0], bb[1]);
                }
#pragma unroll
            for (int mt = 0; mt < 2; mt++)
#pragma unroll
                for (int nt = 0; nt < 8; nt++) {
                    const uint32_t* bb = fb[nt >> 1];
                    if (nt & 1) MMA_BF16(acc[mt][nt], ah[mt], bb[2], bb[3]);
                    else        MMA_BF16(acc[mt][nt], ah[mt], bb[0], bb[1]);
                }
#pragma unroll
            for (int mt = 0; mt < 2; mt++)
                LDSM4(fa[mt], stg + 8192 + (uint32_t)((rowA_base + mt * 16) * 64) + cbA);
#pragma unroll
            for (int mt = 0; mt < 2; mt++)
#pragma unroll
                for (int nt = 0; nt < 8; nt++) {
                    const uint32_t* bb = bh4[nt >> 1];
                    if (nt & 1) MMA_BF16(acc[mt][nt], fa[mt], bb[2], bb[3]);
                    else        MMA_BF16(acc[mt][nt], fa[mt], bb[0], bb[1]);
                }
        }
    }

#pragma unroll
    for (int mt = 0; mt < 2; mt++) {
        const int qi = ib * 128 + wm * 32 + mt * 16 + (lane >> 2);
#pragma unroll
        for (int nt = 0; nt < 8; nt++) {
            const int d = wn * 64 + nt * 8 + ((lane & 3) << 1);
            size_t base0 = (size_t)(b * LL + qi) * DD + h * HD + d;
            size_t base1 = (size_t)(b * LL + qi + 8) * DD + h * HD + d;
            float v0 = acc[mt][nt][0], v1 = acc[mt][nt][1];
            float v2 = acc[mt][nt][2], v3 = acc[mt][nt][3];
            __nv_bfloat16 h0 = __float2bfloat16(v0), h1 = __float2bfloat16(v1);
            __nv_bfloat16 h2 = __float2bfloat16(v2), h3 = __float2bfloat16(v3);
            *(__nv_bfloat162*)(g_ah + base0) = __halves2bfloat162(h0, h1);
            *(__nv_bfloat162*)(g_ah + base1) = __halves2bfloat162(h2, h3);
            *(__nv_bfloat162*)(g_al + base0) = __halves2bfloat162(
                __float2bfloat16(v0 - __bfloat162float(h0)),
                __float2bfloat16(v1 - __bfloat162float(h1)));
            *(__nv_bfloat162*)(g_al + base1) = __halves2bfloat162(
                __float2bfloat16(v2 - __bfloat162float(h2)),
                __float2bfloat16(v3 - __bfloat162float(h3)));
        }
    }
}

// ================= SwiGLU -> split bf16 =================
__global__ void swiglu_split_kernel() {
    size_t idx = (size_t)blockIdx.x * blockDim.x + threadIdx.x;
    if (idx >= (size_t)MROWS * D4) return;
    size_t row = idx >> 13;
    int col = (int)(idx & (D4 - 1));
    float gv = g_p[row * D8 + col];
    float vv = g_p[row * D8 + D4 + col];
    float r = gv / (1.f + expf(-gv)) * vv;
    __nv_bfloat16 hv = __float2bfloat16(r);
    g_ah[idx] = hv;
    g_al[idx] = __float2bfloat16(r - __bfloat162float(hv));
}

// ================= launch =================
extern "C" void kernel_launch(void* const* d_in, const int* in_sizes, int n_in,
                              void* d_out, int out_size) {
    const float* x    = (const float*)d_in[0];
    const float* Wqkv = (const float*)d_in[1];
    const float* bqkv = (const float*)d_in[2];
    const float* Wo   = (const float*)d_in[3];
    const float* bo   = (const float*)d_in[4];
    const float* g1   = (const float*)d_in[5];
    const float* g2   = (const float*)d_in[6];
    const float* Wp   = (const float*)d_in[7];
    const float* bp   = (const float*)d_in[8];
    const float* Wff  = (const float*)d_in[9];
    const float* bff  = (const float*)d_in[10];
    float* out = (float*)d_out;

    __nv_bfloat16 *ah, *al, *wqh, *wql, *woh, *wol, *wph, *wpl, *wfh, *wfl;
    float *qkv, *x1, *p;
    cudaGetSymbolAddress((void**)&ah,  g_ah);
    cudaGetSymbolAddress((void**)&al,  g_al);
    cudaGetSymbolAddress((void**)&wqh, g_WqkvT_hi);
    cudaGetSymbolAddress((void**)&wql, g_WqkvT_lo);
    cudaGetSymbolAddress((void**)&woh, g_WoT_hi);
    cudaGetSymbolAddress((void**)&wol, g_WoT_lo);
    cudaGetSymbolAddress((void**)&wph, g_WpT_hi);
    cudaGetSymbolAddress((void**)&wpl, g_WpT_lo);
    cudaGetSymbolAddress((void**)&wfh, g_WffT_hi);
    cudaGetSymbolAddress((void**)&wfl, g_WffT_lo);
    cudaGetSymbolAddress((void**)&qkv, g_qkv);
    cudaGetSymbolAddress((void**)&x1,  g_x1);
    cudaGetSymbolAddress((void**)&p,   g_p);

    cudaFuncSetAttribute(gemm_mma3_kernel,
                         cudaFuncAttributeMaxDynamicSharedMemorySize, GEMM_SMEM);
    cudaFuncSetAttribute(attn_scores_mma_kernel,
                         cudaFuncAttributeMaxDynamicSharedMemorySize, ATT_SMEM);
    cudaFuncSetAttribute(attn_pv_mma_kernel,
                         cudaFuncAttributeMaxDynamicSharedMemorySize, ATT_SMEM);

    dim3 tb(32, 8);

    // 1) h = rms(x, g1), split
    rmsnorm_split_kernel<<<MROWS, 256>>>(x, g1, ah, al);
    // 2) Wqkv transpose/split
    transpose_split_kernel<<<dim3(D3 / 32, DD / 32), tb>>>(Wqkv, wqh, wql, DD, D3);
    // 3) RoPE tables
    rope_table_kernel<<<LL, 64>>>();
    // 4) qkv = h @ Wqkv + bqkv   (launch #4 — profiled)
    gemm_mma3_kernel<<<dim3(MROWS / TM, D3 / TN), 256, GEMM_SMEM>>>(
        ah, al, wqh, wql, bqkv, nullptr, qkv, MROWS, D3, DD);
    // 5) RoPE apply + split q,k
    {
        int total = BB * LL * HH * 64;
        rope_apply_split_kernel<<<(total + 255) / 256, 256>>>();
    }
    // 6) V transpose + split
    v_transpose_split_kernel<<<dim3(LL / 32, HD / 32, BB * HH), tb>>>();
    // 7) scores
    attn_scores_mma_kernel<<<dim3(LL / 128, LL / 128, BB * HH), 256, ATT_SMEM>>>();
    // 8) softmax -> split P
    softmax_kernel<<<BB * HH * LL, 128>>>();
    // 9) O = P @ V
    attn_pv_mma_kernel<<<dim3(LL / 128, BB * HH), 256, ATT_SMEM>>>();
    // 10) Wo transpose/split
    transpose_split_kernel<<<dim3(DD / 32, DD / 32), tb>>>(Wo, woh, wol, DD, DD);
    // 11) x1 = o @ Wo + bo + x
    gemm_mma3_kernel<<<dim3(MROWS / TM, DD / TN), 256, GEMM_SMEM>>>(
        ah, al, woh, wol, bo, x, x1, MROWS, DD, DD);
    // 12) h2 = rms(x1, g2), split
    rmsnorm_split_kernel<<<MROWS, 256>>>(x1, g2, ah, al);
    // 13) Wp transpose/split
    transpose_split_kernel<<<dim3(D8 / 32, DD / 32), tb>>>(Wp, wph, wpl, DD, D8);
    // 14) p = h2 @ Wp + bp
    gemm_mma3_kernel<<<dim3(MROWS / TM, D8 / TN), 256, GEMM_SMEM>>>(
        ah, al, wph, wpl, bp, nullptr, p, MROWS, D8, DD);
    // 15) ffh = silu(gate) * value, split
    {
        size_t total = (size_t)MROWS * D4;
        swiglu_split_kernel<<<(unsigned)((total + 255) / 256), 256>>>();
    }
    // 16) Wff transpose/split
    transpose_split_kernel<<<dim3(DD / 32, D4 / 32), tb>>>(Wff, wfh, wfl, D4, DD);
    // 17) out = ffh @ Wff + bff + x1
    gemm_mma3_kernel<<<dim3(MROWS / TM, DD / TN), 256, GEMM_SMEM>>>(
        ah, al, wfh, wfl, bff, x1, out, MROWS, DD, D4);
}